// round 5
// baseline (speedup 1.0000x reference)
#include <cuda_runtime.h>
#include <math.h>

// ---------------------------------------------------------------------------
//   B=2, T=1024, D=384 -> d=128, D3=384, D9=1152, NTOK=2048
//   GAMMA=5, EPS_W=1e-8, EPS_N=1e-5
// ---------------------------------------------------------------------------
#define NTOK 2048
#define D3   384
#define D9   1152
#define DD   128
#define HALF_GAMMA 2.5f
#define TANH_SAT 6.5f          // |x|>6.5 -> tanh within 3e-6 of +-1
#define BAND_CAP 64            // tier-1 per-thread band limit

// -------------------- device scratch (static, no allocs) -------------------
__device__ float g_Ft  [3 * DD * D3];       // fused softplus(W)^T * S: [g][k(128)][o(384)]
__device__ float g_fb  [3 * D3];            // fused bias  S^T b
__device__ float g_Wpt [D3 * D9];           // softplus(Wp) transposed: [k(384)][o(1152)]
__device__ float g_QKV [NTOK * D9];         // per-token [Q(384) K(384) V(384)]
__device__ float g_att [NTOK * D3];

// -------------------- helpers ----------------------------------------------
__device__ __forceinline__ float sp_fast(float w) {
    return fmaxf(w, 0.0f) + __logf(1.0f + __expf(-fabsf(w)));
}
__device__ __forceinline__ float fast_tanh(float x) {
    float y; asm("tanh.approx.f32 %0, %1;" : "=f"(y) : "f"(x)); return y;
}

#define LOAD8(dst, rowptr) do {                                               \
    const float4* _r = (const float4*)(rowptr);                               \
    float4 _q0 = _r[0], _q1 = _r[1];                                          \
    dst[0]=_q0.x; dst[1]=_q0.y; dst[2]=_q0.z; dst[3]=_q0.w;                   \
    dst[4]=_q1.x; dst[5]=_q1.y; dst[6]=_q1.z; dst[7]=_q1.w;                   \
} while (0)

// -------------------- K0a: fused softplus+mix  Ft[g][k][o] ------------------
__global__ __launch_bounds__(384) void k_fuse(
        const float* __restrict__ Wq, const float* __restrict__ Wk,
        const float* __restrict__ Wv,
        const float* __restrict__ Sq, const float* __restrict__ Sk,
        const float* __restrict__ Sv) {
    __shared__ float4 ssw[D3];
    const int g  = blockIdx.y;
    const int k0 = blockIdx.x * 4;
    const int tid = threadIdx.x;
    const float* W = (g == 0) ? Wq : (g == 1) ? Wk : Wv;
    const float* S = (g == 0) ? Sq : (g == 1) ? Sk : Sv;

    float4 w = *(const float4*)(W + tid * DD + k0);
    w.x = sp_fast(w.x); w.y = sp_fast(w.y); w.z = sp_fast(w.z); w.w = sp_fast(w.w);
    ssw[tid] = w;
    __syncthreads();

    float4 acc = make_float4(0.f, 0.f, 0.f, 0.f);
#pragma unroll 4
    for (int m = 0; m < D3; m++) {
        float s  = S[m * D3 + tid];
        float4 c = ssw[m];
        acc.x = fmaf(s, c.x, acc.x);
        acc.y = fmaf(s, c.y, acc.y);
        acc.z = fmaf(s, c.z, acc.z);
        acc.w = fmaf(s, c.w, acc.w);
    }
    float* dst = g_Ft + g * (DD * D3) + k0 * D3 + tid;
    dst[0]      = acc.x;
    dst[D3]     = acc.y;
    dst[2 * D3] = acc.z;
    dst[3 * D3] = acc.w;
}

// -------------------- K0b: fused bias (one warp per output) -----------------
__global__ void k_fbias(const float* __restrict__ Sq, const float* __restrict__ Sk,
                        const float* __restrict__ Sv,
                        const float* __restrict__ bq, const float* __restrict__ bk,
                        const float* __restrict__ bv) {
    const int w    = (blockIdx.x * blockDim.x + threadIdx.x) >> 5;
    const int lane = threadIdx.x & 31;
    if (w >= 3 * D3) return;
    const int g = w / D3, o = w - g * D3;
    const float* S = (g == 0) ? Sq : (g == 1) ? Sk : Sv;
    const float* b = (g == 0) ? bq : (g == 1) ? bk : bv;
    float acc = 0.0f;
#pragma unroll
    for (int i = 0; i < 12; i++) {
        int m = lane + i * 32;
        acc = fmaf(S[m * D3 + o], b[m], acc);
    }
#pragma unroll
    for (int off = 16; off > 0; off >>= 1)
        acc += __shfl_down_sync(0xffffffffu, acc, off);
    if (lane == 0) g_fb[w] = acc;
}

// -------------------- K0c: softplus(Wp) transposed --------------------------
__global__ void k_wpt(const float* __restrict__ Wp) {
    __shared__ float tile[32][33];
    const int k0 = blockIdx.x * 32;
    const int o0 = blockIdx.y * 32;
    const int tx = threadIdx.x, ty = threadIdx.y;    // 32 x 8
#pragma unroll
    for (int i = 0; i < 32; i += 8)
        tile[ty + i][tx] = Wp[(o0 + ty + i) * D3 + k0 + tx];
    __syncthreads();
#pragma unroll
    for (int i = 0; i < 32; i += 8)
        g_Wpt[(k0 + ty + i) * D9 + o0 + tx] = sp_fast(tile[tx][ty + i]);
}

// -------------------- K1: QKV projection (8 tokens/CTA, 2 CTA/SM) -----------
__global__ __launch_bounds__(384, 2) void k_qkv(const float* __restrict__ x) {
    __shared__ float sx[D3][12];                     // 48B rows (16B aligned)
    const int t0  = blockIdx.x * 8;
    const int tid = threadIdx.x;

#pragma unroll
    for (int m = 0; m < 8; m++)
        sx[tid][m] = x[(t0 + m) * D3 + tid];
    __syncthreads();

    float a0[8], a1[8], a2[8];
#pragma unroll
    for (int m = 0; m < 8; m++) { a0[m] = 0.f; a1[m] = 0.f; a2[m] = 0.f; }

    const float* F0 = g_Ft + 0 * (DD * D3) + tid;
    const float* F1 = g_Ft + 1 * (DD * D3) + tid;
    const float* F2 = g_Ft + 2 * (DD * D3) + tid;

    float xv[8];
#pragma unroll 4
    for (int k = 0; k < DD; k++) {
        float w0 = F0[k * D3];
        float w1 = F1[k * D3];
        float w2 = F2[k * D3];
        LOAD8(xv, &sx[k][0]);
#pragma unroll
        for (int m = 0; m < 8; m++) a0[m] = fmaf(xv[m], w0, a0[m]);
        LOAD8(xv, &sx[128 + k][0]);
#pragma unroll
        for (int m = 0; m < 8; m++) a1[m] = fmaf(xv[m], w1, a1[m]);
        LOAD8(xv, &sx[256 + k][0]);
#pragma unroll
        for (int m = 0; m < 8; m++) a2[m] = fmaf(xv[m], w2, a2[m]);
    }
    const float b0 = g_fb[tid], b1 = g_fb[D3 + tid], b2 = g_fb[2 * D3 + tid];
#pragma unroll
    for (int m = 0; m < 8; m++) {
        float* q = g_QKV + (t0 + m) * D9;
        q[tid]          = a0[m] + b0;
        q[D3 + tid]     = a1[m] + b1;
        q[2 * D3 + tid] = a2[m] + b2;
    }
}

// -------------------- K2: banded sigmoid-outer attention --------------------
// s = 0.5 + 0.5*tanh(q * c_j), c_j = 2.5*k_j.  tanh saturates for |q*c|>6.5.
// Sort (c,v) per token; saturated tails come from prefix sums; only the band
// |c| <= 6.5/|q| is evaluated. Tier1: per-thread (band<=CAP). Tier2: warp/query.
__global__ __launch_bounds__(384) void k_attn() {
    __shared__ float2 s[512];          // sorted (c,v); pads at 384..511
    __shared__ float  Pv[385];         // exclusive prefix sums of sorted v
    __shared__ float  wsum[12];
    __shared__ int    biglist[384];
    __shared__ int    bigcount;
    const int t    = blockIdx.x;
    const int tid  = threadIdx.x;
    const int lane = tid & 31, wid = tid >> 5;
    const float* base = g_QKV + t * D9;

    s[tid] = make_float2(base[D3 + tid] * HALF_GAMMA, base[2 * D3 + tid]);
    if (tid < 128) s[384 + tid] = make_float2(1e30f, 0.0f);
    if (tid == 0) bigcount = 0;

    // ---- bitonic sort (512 elems, ascending in .x) ----
    for (int k = 2; k <= 512; k <<= 1) {
        for (int j = k >> 1; j > 0; j >>= 1) {
            __syncthreads();
#pragma unroll 2
            for (int i = tid; i < 512; i += 384) {
                int ixj = i ^ j;
                if (ixj > i) {
                    float2 a = s[i], b = s[ixj];
                    bool up = ((i & k) == 0);
                    if ((a.x > b.x) == up) { s[i] = b; s[ixj] = a; }
                }
            }
        }
    }
    __syncthreads();

    // ---- exclusive prefix sums of sorted v ----
    {
        float v = s[tid].y;
        float inc = v;
#pragma unroll
        for (int o = 1; o < 32; o <<= 1) {
            float n = __shfl_up_sync(0xffffffffu, inc, o);
            if (lane >= o) inc += n;
        }
        if (lane == 31) wsum[wid] = inc;
        __syncthreads();
        float woff = 0.f;
        for (int w = 0; w < wid; w++) woff += wsum[w];
        Pv[tid + 1] = inc + woff;
        if (tid == 0) Pv[0] = 0.f;
    }
    __syncthreads();
    const float sumV = Pv[384];

    // ---- per-query band ----
    const float q  = base[tid];
    const float aq = fabsf(q);
    const float th = TANH_SAT / aq;                 // +inf when q == 0
    const float sg = (q >= 0.f) ? 1.f : -1.f;
    int lo, hi;
    { int l = 0, h = 384; while (l < h) { int m = (l + h) >> 1; if (s[m].x < -th) l = m + 1; else h = m; } lo = l; }
    { int l = 0, h = 384; while (l < h) { int m = (l + h) >> 1; if (s[m].x <= th) l = m + 1; else h = m; } hi = l; }

    const int blen = hi - lo;
    if (blen <= BAND_CAP) {
        float ts = sg * (float)((384 - hi) - lo);
        float tv = sg * (sumV - Pv[hi] - Pv[lo]);
        for (int j = lo; j < hi; j++) {
            float2 cv = s[j];
            float tt = fast_tanh(q * cv.x);
            tv = fmaf(tt, cv.y, tv);
            ts += tt;
        }
        float num = fmaf(0.5f, tv, 0.5f * sumV);
        float den = fmaf(0.5f, ts, 192.0f + 1e-8f);
        g_att[t * D3 + tid] = num / den;
    } else {
        int idx = atomicAdd(&bigcount, 1);
        biglist[idx] = tid | (lo << 9) | (hi << 18);   // all fields <= 384 < 512
    }
    __syncthreads();

    // ---- tier 2: one warp per large-band query ----
    const int nbig = bigcount;
    for (int b = wid; b < nbig; b += 12) {
        const int e  = biglist[b];
        const int i  = e & 511;
        const int l2 = (e >> 9) & 511;
        const int h2 = (e >> 18) & 511;
        const float qq  = base[i];
        const float sg2 = (qq >= 0.f) ? 1.f : -1.f;
        float tvb = 0.f, tsb = 0.f;
        for (int j = l2 + lane; j < h2; j += 32) {
            float2 cv = s[j];
            float tt = fast_tanh(qq * cv.x);
            tvb = fmaf(tt, cv.y, tvb);
            tsb += tt;
        }
#pragma unroll
        for (int o = 16; o > 0; o >>= 1) {
            tvb += __shfl_down_sync(0xffffffffu, tvb, o);
            tsb += __shfl_down_sync(0xffffffffu, tsb, o);
        }
        if (lane == 0) {
            float ts = sg2 * (float)((384 - h2) - l2) + tsb;
            float tv = sg2 * (sumV - Pv[h2] - Pv[l2]) + tvb;
            float num = fmaf(0.5f, tv, 0.5f * sumV);
            float den = fmaf(0.5f, ts, 192.0f + 1e-8f);
            g_att[t * D3 + i] = num / den;
        }
    }
}

// -------------------- K3: h = att @ Wpt + bp, fused LayerNorm ---------------
__global__ __launch_bounds__(384, 2) void k_gemm3ln(const float* __restrict__ bp,
                                                    const float* __restrict__ gn,
                                                    const float* __restrict__ bn,
                                                    float* __restrict__ out) {
    __shared__ float sa[D3][12];
    __shared__ float red[8][13];
    __shared__ float smu[8], srs[8];
    const int t0  = blockIdx.x * 8;
    const int tid = threadIdx.x;
    const int lane = tid & 31, wid = tid >> 5;

#pragma unroll
    for (int m = 0; m < 8; m++)
        sa[tid][m] = g_att[(t0 + m) * D3 + tid];
    __syncthreads();

    float a0[8], a1[8], a2[8];
#pragma unroll
    for (int m = 0; m < 8; m++) { a0[m] = 0.f; a1[m] = 0.f; a2[m] = 0.f; }

    float xv[8];
#pragma unroll 4
    for (int k = 0; k < D3; k++) {
        const float* w = g_Wpt + k * D9 + tid;
        float w0 = w[0];
        float w1 = w[D3];
        float w2 = w[2 * D3];
        LOAD8(xv, &sa[k][0]);
#pragma unroll
        for (int m = 0; m < 8; m++) {
            a0[m] = fmaf(xv[m], w0, a0[m]);
            a1[m] = fmaf(xv[m], w1, a1[m]);
            a2[m] = fmaf(xv[m], w2, a2[m]);
        }
    }
    const float b0 = bp[tid], b1 = bp[D3 + tid], b2 = bp[2 * D3 + tid];
#pragma unroll
    for (int m = 0; m < 8; m++) { a0[m] += b0; a1[m] += b1; a2[m] += b2; }

    // ---- mean ----
#pragma unroll
    for (int m = 0; m < 8; m++) {
        float sred = a0[m] + a1[m] + a2[m];
#pragma unroll
        for (int off = 16; off > 0; off >>= 1)
            sred += __shfl_down_sync(0xffffffffu, sred, off);
        if (lane == 0) red[m][wid] = sred;
    }
    __syncthreads();
    if (tid < 8) {
        float tot = 0.f;
#pragma unroll
        for (int i = 0; i < 12; i++) tot += red[tid][i];
        smu[tid] = tot * (1.0f / 1152.0f);
    }
    __syncthreads();

    // ---- variance (two-pass) ----
#pragma unroll
    for (int m = 0; m < 8; m++) {
        float mu = smu[m];
        float d0 = a0[m] - mu, d1 = a1[m] - mu, d2 = a2[m] - mu;
        float sred = d0 * d0 + d1 * d1 + d2 * d2;
#pragma unroll
        for (int off = 16; off > 0; off >>= 1)
            sred += __shfl_down_sync(0xffffffffu, sred, off);
        if (lane == 0) red[m][wid] = sred;
    }
    __syncthreads();
    if (tid < 8) {
        float tot = 0.f;
#pragma unroll
        for (int i = 0; i < 12; i++) tot += red[tid][i];
        srs[tid] = rsqrtf(tot * (1.0f / 1152.0f) + 1e-5f);
    }
    __syncthreads();

    const float g0 = gn[tid], g1 = gn[D3 + tid], g2 = gn[2 * D3 + tid];
    const float n0 = bn[tid], n1 = bn[D3 + tid], n2 = bn[2 * D3 + tid];
#pragma unroll
    for (int m = 0; m < 8; m++) {
        float mu = smu[m], rs = srs[m];
        float* o = out + (t0 + m) * D9;
        o[tid]          = (a0[m] - mu) * rs * g0 + n0;
        o[D3 + tid]     = (a1[m] - mu) * rs * g1 + n1;
        o[2 * D3 + tid] = (a2[m] - mu) * rs * g2 + n2;
    }
}

// -------------------- launch -------------------------------------------------
extern "C" void kernel_launch(void* const* d_in, const int* in_sizes, int n_in,
                              void* d_out, int out_size) {
    const float* x  = (const float*)d_in[0];
    const float* Wq = (const float*)d_in[1];
    const float* bq = (const float*)d_in[2];
    const float* Sq = (const float*)d_in[3];
    const float* Wk = (const float*)d_in[4];
    const float* bk = (const float*)d_in[5];
    const float* Sk = (const float*)d_in[6];
    const float* Wv = (const float*)d_in[7];
    const float* bv = (const float*)d_in[8];
    const float* Sv = (const float*)d_in[9];
    const float* Wp = (const float*)d_in[10];
    const float* bp = (const float*)d_in[11];
    const float* gn = (const float*)d_in[12];
    const float* bn = (const float*)d_in[13];
    float* out = (float*)d_out;

    // order chosen so launch #4 (ncu -s 5 window) is k_attn
    k_fuse  <<<dim3(32, 3), 384>>>(Wq, Wk, Wv, Sq, Sk, Sv);
    k_fbias <<<144, 256>>>(Sq, Sk, Sv, bq, bk, bv);
    k_qkv   <<<NTOK / 8, 384>>>(x);
    k_attn  <<<NTOK, 384>>>();
    k_wpt   <<<dim3(12, 36), dim3(32, 8)>>>(Wp);
    k_gemm3ln<<<NTOK / 8, 384>>>(bp, gn, bn, out);
}

// round 6
// speedup vs baseline: 1.1655x; 1.1655x over previous
#include <cuda_runtime.h>
#include <math.h>

// ---------------------------------------------------------------------------
//   B=2, T=1024, D=384 -> d=128, D3=384, D9=1152, NTOK=2048
//   GAMMA=5, EPS_W=1e-8, EPS_N=1e-5
// ---------------------------------------------------------------------------
#define NTOK 2048
#define D3   384
#define D9   1152
#define DD   128
#define HALF_GAMMA 2.5f
#define TANH_SAT 6.5f          // |x|>6.5 -> tanh within 3e-6 of +-1
#define BAND_CAP 64            // tier-1 per-thread band limit
#define NBINS 128

// -------------------- device scratch (static, no allocs) -------------------
__device__ float g_Ft  [3 * DD * D3];       // fused softplus(W)^T * S: [g][k(128)][o(384)]
__device__ float g_fb  [3 * D3];            // fused bias  S^T b
__device__ float g_Wpt [D3 * D9];           // softplus(Wp) transposed: [k(384)][o(1152)]
__device__ float g_QKV [NTOK * D9];         // per-token [Q(384) K(384) V(384)]
__device__ float g_att [NTOK * D3];

// -------------------- helpers ----------------------------------------------
__device__ __forceinline__ float sp_fast(float w) {
    return fmaxf(w, 0.0f) + __logf(1.0f + __expf(-fabsf(w)));
}
__device__ __forceinline__ float fast_tanh(float x) {
    float y; asm("tanh.approx.f32 %0, %1;" : "=f"(y) : "f"(x)); return y;
}

#define LOAD8(dst, rowptr) do {                                               \
    const float4* _r = (const float4*)(rowptr);                               \
    float4 _q0 = _r[0], _q1 = _r[1];                                          \
    dst[0]=_q0.x; dst[1]=_q0.y; dst[2]=_q0.z; dst[3]=_q0.w;                   \
    dst[4]=_q1.x; dst[5]=_q1.y; dst[6]=_q1.z; dst[7]=_q1.w;                   \
} while (0)

// -------------------- K0a: fused softplus+mix  Ft[g][k][o] ------------------
__global__ __launch_bounds__(384) void k_fuse(
        const float* __restrict__ Wq, const float* __restrict__ Wk,
        const float* __restrict__ Wv,
        const float* __restrict__ Sq, const float* __restrict__ Sk,
        const float* __restrict__ Sv) {
    __shared__ float4 ssw[D3];
    const int g  = blockIdx.y;
    const int k0 = blockIdx.x * 4;
    const int tid = threadIdx.x;
    const float* W = (g == 0) ? Wq : (g == 1) ? Wk : Wv;
    const float* S = (g == 0) ? Sq : (g == 1) ? Sk : Sv;

    float4 w = *(const float4*)(W + tid * DD + k0);
    w.x = sp_fast(w.x); w.y = sp_fast(w.y); w.z = sp_fast(w.z); w.w = sp_fast(w.w);
    ssw[tid] = w;
    __syncthreads();

    float4 acc = make_float4(0.f, 0.f, 0.f, 0.f);
#pragma unroll 4
    for (int m = 0; m < D3; m++) {
        float s  = S[m * D3 + tid];
        float4 c = ssw[m];
        acc.x = fmaf(s, c.x, acc.x);
        acc.y = fmaf(s, c.y, acc.y);
        acc.z = fmaf(s, c.z, acc.z);
        acc.w = fmaf(s, c.w, acc.w);
    }
    float* dst = g_Ft + g * (DD * D3) + k0 * D3 + tid;
    dst[0]      = acc.x;
    dst[D3]     = acc.y;
    dst[2 * D3] = acc.z;
    dst[3 * D3] = acc.w;
}

// -------------------- K0b: fused bias (one warp per output) -----------------
__global__ void k_fbias(const float* __restrict__ Sq, const float* __restrict__ Sk,
                        const float* __restrict__ Sv,
                        const float* __restrict__ bq, const float* __restrict__ bk,
                        const float* __restrict__ bv) {
    const int w    = (blockIdx.x * blockDim.x + threadIdx.x) >> 5;
    const int lane = threadIdx.x & 31;
    if (w >= 3 * D3) return;
    const int g = w / D3, o = w - g * D3;
    const float* S = (g == 0) ? Sq : (g == 1) ? Sk : Sv;
    const float* b = (g == 0) ? bq : (g == 1) ? bk : bv;
    float acc = 0.0f;
#pragma unroll
    for (int i = 0; i < 12; i++) {
        int m = lane + i * 32;
        acc = fmaf(S[m * D3 + o], b[m], acc);
    }
#pragma unroll
    for (int off = 16; off > 0; off >>= 1)
        acc += __shfl_down_sync(0xffffffffu, acc, off);
    if (lane == 0) g_fb[w] = acc;
}

// -------------------- K0c: softplus(Wp) transposed --------------------------
__global__ void k_wpt(const float* __restrict__ Wp) {
    __shared__ float tile[32][33];
    const int k0 = blockIdx.x * 32;
    const int o0 = blockIdx.y * 32;
    const int tx = threadIdx.x, ty = threadIdx.y;    // 32 x 8
#pragma unroll
    for (int i = 0; i < 32; i += 8)
        tile[ty + i][tx] = Wp[(o0 + ty + i) * D3 + k0 + tx];
    __syncthreads();
#pragma unroll
    for (int i = 0; i < 32; i += 8)
        g_Wpt[(k0 + ty + i) * D9 + o0 + tx] = sp_fast(tile[tx][ty + i]);
}

// -------------------- K1: QKV projection (8 tokens/CTA, 2 CTA/SM) -----------
__global__ __launch_bounds__(384, 2) void k_qkv(const float* __restrict__ x) {
    __shared__ float sx[D3][12];
    const int t0  = blockIdx.x * 8;
    const int tid = threadIdx.x;

#pragma unroll
    for (int m = 0; m < 8; m++)
        sx[tid][m] = x[(t0 + m) * D3 + tid];
    __syncthreads();

    float a0[8], a1[8], a2[8];
#pragma unroll
    for (int m = 0; m < 8; m++) { a0[m] = 0.f; a1[m] = 0.f; a2[m] = 0.f; }

    const float* F0 = g_Ft + 0 * (DD * D3) + tid;
    const float* F1 = g_Ft + 1 * (DD * D3) + tid;
    const float* F2 = g_Ft + 2 * (DD * D3) + tid;

    float xv[8];
#pragma unroll 4
    for (int k = 0; k < DD; k++) {
        float w0 = F0[k * D3];
        float w1 = F1[k * D3];
        float w2 = F2[k * D3];
        LOAD8(xv, &sx[k][0]);
#pragma unroll
        for (int m = 0; m < 8; m++) a0[m] = fmaf(xv[m], w0, a0[m]);
        LOAD8(xv, &sx[128 + k][0]);
#pragma unroll
        for (int m = 0; m < 8; m++) a1[m] = fmaf(xv[m], w1, a1[m]);
        LOAD8(xv, &sx[256 + k][0]);
#pragma unroll
        for (int m = 0; m < 8; m++) a2[m] = fmaf(xv[m], w2, a2[m]);
    }
    const float b0 = g_fb[tid], b1 = g_fb[D3 + tid], b2 = g_fb[2 * D3 + tid];
#pragma unroll
    for (int m = 0; m < 8; m++) {
        float* q = g_QKV + (t0 + m) * D9;
        q[tid]          = a0[m] + b0;
        q[D3 + tid]     = a1[m] + b1;
        q[2 * D3 + tid] = a2[m] + b2;
    }
}

// -------------------- K2: banded attention via COUNTING SORT ----------------
// s_ij = 0.5 + 0.5*tanh(q_i * c_j), c_j = 2.5*k_j; tanh saturates |x|>6.5.
// Counting-sort (c,v) into 128 value bins (O(n), no bitonic). Saturated tails
// via prefix sums at bin boundaries; only the band bins get real tanh.
__global__ __launch_bounds__(384) void k_attn() {
    __shared__ float2 s[D3];           // bin-grouped (c,v)
    __shared__ float  Pv[D3 + 1];      // exclusive prefix sums of grouped v
    __shared__ int    off[NBINS + 1];  // bin start offsets (exclusive scan)
    __shared__ int    cnt[NBINS];
    __shared__ int    cur[NBINS];
    __shared__ int    wtot[4];
    __shared__ float  wsum[12];
    __shared__ float  rmin[12], rmax[12];
    __shared__ float  s_cmin, s_inv;
    __shared__ int    biglist[D3];
    __shared__ int    bigcount;

    const int t    = blockIdx.x;
    const int tid  = threadIdx.x;
    const int lane = tid & 31, wid = tid >> 5;
    const float* base = g_QKV + t * D9;

    const float c = base[D3 + tid] * HALF_GAMMA;
    const float v = base[2 * D3 + tid];

    // ---- block min/max of c ----
    float mn = c, mx = c;
#pragma unroll
    for (int o = 16; o > 0; o >>= 1) {
        mn = fminf(mn, __shfl_down_sync(0xffffffffu, mn, o));
        mx = fmaxf(mx, __shfl_down_sync(0xffffffffu, mx, o));
    }
    if (lane == 0) { rmin[wid] = mn; rmax[wid] = mx; }
    if (tid < NBINS) cnt[tid] = 0;
    if (tid == 0) bigcount = 0;
    __syncthreads();
    if (tid == 0) {
        float cmin = rmin[0], cmax = rmax[0];
#pragma unroll
        for (int i = 1; i < 12; i++) {
            cmin = fminf(cmin, rmin[i]);
            cmax = fmaxf(cmax, rmax[i]);
        }
        s_cmin = cmin;
        s_inv  = 127.99f / (cmax - cmin + 1e-12f);
    }
    __syncthreads();
    const float cmin = s_cmin, inv = s_inv;

    // ---- count ----
    int b = (int)((c - cmin) * inv);
    b = min(NBINS - 1, max(0, b));
    atomicAdd(&cnt[b], 1);
    __syncthreads();

    // ---- exclusive scan of cnt (128 entries, 4 warps) ----
    {
        int xval = (tid < NBINS) ? cnt[tid] : 0;
        int incl = xval;
#pragma unroll
        for (int o = 1; o < 32; o <<= 1) {
            int n = __shfl_up_sync(0xffffffffu, incl, o);
            if (lane >= o) incl += n;
        }
        if (tid < NBINS && lane == 31) wtot[wid] = incl;
        __syncthreads();
        if (tid < NBINS) {
            int add = 0;
#pragma unroll
            for (int w = 0; w < 4; w++) if (w < wid) add += wtot[w];
            off[tid + 1] = incl + add;
            cur[tid]     = incl + add - xval;     // exclusive start = cursor
        }
        if (tid == 0) off[0] = 0;
    }
    __syncthreads();

    // ---- scatter into bin groups ----
    int pos = atomicAdd(&cur[b], 1);
    s[pos] = make_float2(c, v);
    __syncthreads();

    // ---- exclusive prefix sums of grouped v ----
    {
        float inc = s[tid].y;
#pragma unroll
        for (int o = 1; o < 32; o <<= 1) {
            float n = __shfl_up_sync(0xffffffffu, inc, o);
            if (lane >= o) inc += n;
        }
        if (lane == 31) wsum[wid] = inc;
        __syncthreads();
        float add = 0.f;
#pragma unroll
        for (int w = 0; w < 12; w++) if (w < wid) add += wsum[w];
        Pv[tid + 1] = inc + add;
        if (tid == 0) Pv[0] = 0.f;
    }
    __syncthreads();
    const float sumV = Pv[D3];

    // ---- per-query band from bin edges ----
    const float q  = base[tid];
    const float th = TANH_SAT / fabsf(q);            // +inf when q == 0
    const float sg = (q >= 0.f) ? 1.f : -1.f;
    // bins strictly below lob have c < -th; bins strictly above hib have c > th
    float lof = floorf((-th - cmin) * inv);
    float hif = floorf(( th - cmin) * inv) + 1.0f;
    lof = fminf(fmaxf(lof, 0.0f), 128.0f);
    hif = fminf(fmaxf(hif, 0.0f), 128.0f);
    const int loIdx = off[(int)lof];
    const int hiIdx = off[(int)hif];

    const int blen = hiIdx - loIdx;
    if (blen <= BAND_CAP) {
        float ts = sg * (float)((D3 - hiIdx) - loIdx);
        float tv = sg * (sumV - Pv[hiIdx] - Pv[loIdx]);
        for (int j = loIdx; j < hiIdx; j++) {
            float2 cv = s[j];
            float tt = fast_tanh(q * cv.x);
            tv = fmaf(tt, cv.y, tv);
            ts += tt;
        }
        float num = fmaf(0.5f, tv, 0.5f * sumV);
        float den = fmaf(0.5f, ts, 192.0f + 1e-8f);
        g_att[t * D3 + tid] = num / den;
    } else {
        int idx = atomicAdd(&bigcount, 1);
        biglist[idx] = tid | (loIdx << 9) | (hiIdx << 18);
    }
    __syncthreads();

    // ---- tier 2: one warp per large-band query ----
    const int nbig = bigcount;
    for (int bq2 = wid; bq2 < nbig; bq2 += 12) {
        const int e  = biglist[bq2];
        const int i  = e & 511;
        const int l2 = (e >> 9) & 511;
        const int h2 = (e >> 18) & 511;
        const float qq  = base[i];
        const float sg2 = (qq >= 0.f) ? 1.f : -1.f;
        float tvb = 0.f, tsb = 0.f;
        for (int j = l2 + lane; j < h2; j += 32) {
            float2 cv = s[j];
            float tt = fast_tanh(qq * cv.x);
            tvb = fmaf(tt, cv.y, tvb);
            tsb += tt;
        }
#pragma unroll
        for (int o = 16; o > 0; o >>= 1) {
            tvb += __shfl_down_sync(0xffffffffu, tvb, o);
            tsb += __shfl_down_sync(0xffffffffu, tsb, o);
        }
        if (lane == 0) {
            float ts = sg2 * (float)((D3 - h2) - l2) + tsb;
            float tv = sg2 * (sumV - Pv[h2] - Pv[l2]) + tvb;
            float num = fmaf(0.5f, tv, 0.5f * sumV);
            float den = fmaf(0.5f, ts, 192.0f + 1e-8f);
            g_att[t * D3 + i] = num / den;
        }
    }
}

// -------------------- K3: h = att @ Wpt + bp, fused LayerNorm ---------------
__global__ __launch_bounds__(384, 2) void k_gemm3ln(const float* __restrict__ bp,
                                                    const float* __restrict__ gn,
                                                    const float* __restrict__ bn,
                                                    float* __restrict__ out) {
    __shared__ float sa[D3][12];
    __shared__ float red[8][13];
    __shared__ float smu[8], srs[8];
    const int t0  = blockIdx.x * 8;
    const int tid = threadIdx.x;
    const int lane = tid & 31, wid = tid >> 5;

#pragma unroll
    for (int m = 0; m < 8; m++)
        sa[tid][m] = g_att[(t0 + m) * D3 + tid];
    __syncthreads();

    float a0[8], a1[8], a2[8];
#pragma unroll
    for (int m = 0; m < 8; m++) { a0[m] = 0.f; a1[m] = 0.f; a2[m] = 0.f; }

    float xv[8];
#pragma unroll 4
    for (int k = 0; k < D3; k++) {
        const float* w = g_Wpt + k * D9 + tid;
        float w0 = w[0];
        float w1 = w[D3];
        float w2 = w[2 * D3];
        LOAD8(xv, &sa[k][0]);
#pragma unroll
        for (int m = 0; m < 8; m++) {
            a0[m] = fmaf(xv[m], w0, a0[m]);
            a1[m] = fmaf(xv[m], w1, a1[m]);
            a2[m] = fmaf(xv[m], w2, a2[m]);
        }
    }
    const float b0 = bp[tid], b1 = bp[D3 + tid], b2 = bp[2 * D3 + tid];
#pragma unroll
    for (int m = 0; m < 8; m++) { a0[m] += b0; a1[m] += b1; a2[m] += b2; }

    // ---- mean ----
#pragma unroll
    for (int m = 0; m < 8; m++) {
        float sred = a0[m] + a1[m] + a2[m];
#pragma unroll
        for (int off = 16; off > 0; off >>= 1)
            sred += __shfl_down_sync(0xffffffffu, sred, off);
        if (lane == 0) red[m][wid] = sred;
    }
    __syncthreads();
    if (tid < 8) {
        float tot = 0.f;
#pragma unroll
        for (int i = 0; i < 12; i++) tot += red[tid][i];
        smu[tid] = tot * (1.0f / 1152.0f);
    }
    __syncthreads();

    // ---- variance (two-pass) ----
#pragma unroll
    for (int m = 0; m < 8; m++) {
        float mu = smu[m];
        float d0 = a0[m] - mu, d1 = a1[m] - mu, d2 = a2[m] - mu;
        float sred = d0 * d0 + d1 * d1 + d2 * d2;
#pragma unroll
        for (int off = 16; off > 0; off >>= 1)
            sred += __shfl_down_sync(0xffffffffu, sred, off);
        if (lane == 0) red[m][wid] = sred;
    }
    __syncthreads();
    if (tid < 8) {
        float tot = 0.f;
#pragma unroll
        for (int i = 0; i < 12; i++) tot += red[tid][i];
        srs[tid] = rsqrtf(tot * (1.0f / 1152.0f) + 1e-5f);
    }
    __syncthreads();

    const float g0 = gn[tid], g1 = gn[D3 + tid], g2 = gn[2 * D3 + tid];
    const float n0 = bn[tid], n1 = bn[D3 + tid], n2 = bn[2 * D3 + tid];
#pragma unroll
    for (int m = 0; m < 8; m++) {
        float mu = smu[m], rs = srs[m];
        float* o = out + (t0 + m) * D9;
        o[tid]          = (a0[m] - mu) * rs * g0 + n0;
        o[D3 + tid]     = (a1[m] - mu) * rs * g1 + n1;
        o[2 * D3 + tid] = (a2[m] - mu) * rs * g2 + n2;
    }
}

// -------------------- launch -------------------------------------------------
extern "C" void kernel_launch(void* const* d_in, const int* in_sizes, int n_in,
                              void* d_out, int out_size) {
    const float* x  = (const float*)d_in[0];
    const float* Wq = (const float*)d_in[1];
    const float* bq = (const float*)d_in[2];
    const float* Sq = (const float*)d_in[3];
    const float* Wk = (const float*)d_in[4];
    const float* bk = (const float*)d_in[5];
    const float* Sk = (const float*)d_in[6];
    const float* Wv = (const float*)d_in[7];
    const float* bv = (const float*)d_in[8];
    const float* Sv = (const float*)d_in[9];
    const float* Wp = (const float*)d_in[10];
    const float* bp = (const float*)d_in[11];
    const float* gn = (const float*)d_in[12];
    const float* bn = (const float*)d_in[13];
    float* out = (float*)d_out;

    // order chosen so the profiled (4th) launch is k_attn again
    k_fuse  <<<dim3(32, 3), 384>>>(Wq, Wk, Wv, Sq, Sk, Sv);
    k_fbias <<<144, 256>>>(Sq, Sk, Sv, bq, bk, bv);
    k_qkv   <<<NTOK / 8, 384>>>(x);
    k_attn  <<<NTOK, 384>>>();
    k_wpt   <<<dim3(12, 36), dim3(32, 8)>>>(Wp);
    k_gemm3ln<<<NTOK / 8, 384>>>(bp, gn, bn, out);
}

// round 7
// speedup vs baseline: 1.4690x; 1.2604x over previous
#include <cuda_runtime.h>
#include <math.h>

// ---------------------------------------------------------------------------
//   B=2, T=1024, D=384 -> d=128, D3=384, D9=1152, NTOK=2048
//   GAMMA=5, EPS_W=1e-8, EPS_N=1e-5
// ---------------------------------------------------------------------------
#define NTOK 2048
#define D3   384
#define D9   1152
#define DD   128
#define HALF_GAMMA 2.5f
#define TANH_SAT 6.5f          // |x|>6.5 -> tanh within 3e-6 of +-1
#define NBINS 128

// -------------------- device scratch (static, no allocs) -------------------
__device__ float g_Ft  [3 * DD * D3];       // fused softplus(W)^T * S: [g][k(128)][o(384)]
__device__ float g_fb  [3 * D3];            // fused bias  S^T b
__device__ float g_Wpt [D3 * D9];           // softplus(Wp) transposed: [k(384)][o(1152)]
__device__ float g_QKV [NTOK * D9];         // per-token [Q(384) K(384) V(384)]
__device__ float g_att [NTOK * D3];

// -------------------- helpers ----------------------------------------------
__device__ __forceinline__ float sp_fast(float w) {
    return fmaxf(w, 0.0f) + __logf(1.0f + __expf(-fabsf(w)));
}
__device__ __forceinline__ float fast_tanh(float x) {
    float y; asm("tanh.approx.f32 %0, %1;" : "=f"(y) : "f"(x)); return y;
}

#define LOAD8(dst, rowptr) do {                                               \
    const float4* _r = (const float4*)(rowptr);                               \
    float4 _q0 = _r[0], _q1 = _r[1];                                          \
    dst[0]=_q0.x; dst[1]=_q0.y; dst[2]=_q0.z; dst[3]=_q0.w;                   \
    dst[4]=_q1.x; dst[5]=_q1.y; dst[6]=_q1.z; dst[7]=_q1.w;                   \
} while (0)

// -------------------- K0a: fused softplus+mix  Ft[g][k][o] ------------------
__global__ __launch_bounds__(384) void k_fuse(
        const float* __restrict__ Wq, const float* __restrict__ Wk,
        const float* __restrict__ Wv,
        const float* __restrict__ Sq, const float* __restrict__ Sk,
        const float* __restrict__ Sv) {
    __shared__ float4 ssw[D3];
    const int g  = blockIdx.y;
    const int k0 = blockIdx.x * 4;
    const int tid = threadIdx.x;
    const float* W = (g == 0) ? Wq : (g == 1) ? Wk : Wv;
    const float* S = (g == 0) ? Sq : (g == 1) ? Sk : Sv;

    float4 w = *(const float4*)(W + tid * DD + k0);
    w.x = sp_fast(w.x); w.y = sp_fast(w.y); w.z = sp_fast(w.z); w.w = sp_fast(w.w);
    ssw[tid] = w;
    __syncthreads();

    float4 acc = make_float4(0.f, 0.f, 0.f, 0.f);
#pragma unroll 4
    for (int m = 0; m < D3; m++) {
        float s  = S[m * D3 + tid];
        float4 c = ssw[m];
        acc.x = fmaf(s, c.x, acc.x);
        acc.y = fmaf(s, c.y, acc.y);
        acc.z = fmaf(s, c.z, acc.z);
        acc.w = fmaf(s, c.w, acc.w);
    }
    float* dst = g_Ft + g * (DD * D3) + k0 * D3 + tid;
    dst[0]      = acc.x;
    dst[D3]     = acc.y;
    dst[2 * D3] = acc.z;
    dst[3 * D3] = acc.w;
}

// -------------------- K0b: fused bias (one warp per output) -----------------
__global__ void k_fbias(const float* __restrict__ Sq, const float* __restrict__ Sk,
                        const float* __restrict__ Sv,
                        const float* __restrict__ bq, const float* __restrict__ bk,
                        const float* __restrict__ bv) {
    const int w    = (blockIdx.x * blockDim.x + threadIdx.x) >> 5;
    const int lane = threadIdx.x & 31;
    if (w >= 3 * D3) return;
    const int g = w / D3, o = w - g * D3;
    const float* S = (g == 0) ? Sq : (g == 1) ? Sk : Sv;
    const float* b = (g == 0) ? bq : (g == 1) ? bk : bv;
    float acc = 0.0f;
#pragma unroll
    for (int i = 0; i < 12; i++) {
        int m = lane + i * 32;
        acc = fmaf(S[m * D3 + o], b[m], acc);
    }
#pragma unroll
    for (int off = 16; off > 0; off >>= 1)
        acc += __shfl_down_sync(0xffffffffu, acc, off);
    if (lane == 0) g_fb[w] = acc;
}

// -------------------- K0c: softplus(Wp) transposed --------------------------
__global__ void k_wpt(const float* __restrict__ Wp) {
    __shared__ float tile[32][33];
    const int k0 = blockIdx.x * 32;
    const int o0 = blockIdx.y * 32;
    const int tx = threadIdx.x, ty = threadIdx.y;    // 32 x 8
#pragma unroll
    for (int i = 0; i < 32; i += 8)
        tile[ty + i][tx] = Wp[(o0 + ty + i) * D3 + k0 + tx];
    __syncthreads();
#pragma unroll
    for (int i = 0; i < 32; i += 8)
        g_Wpt[(k0 + ty + i) * D9 + o0 + tx] = sp_fast(tile[tx][ty + i]);
}

// -------------------- K1: QKV projection (8 tokens/CTA, 2 CTA/SM) -----------
__global__ __launch_bounds__(384, 2) void k_qkv(const float* __restrict__ x) {
    __shared__ float sx[D3][12];
    const int t0  = blockIdx.x * 8;
    const int tid = threadIdx.x;

#pragma unroll
    for (int m = 0; m < 8; m++)
        sx[tid][m] = x[(t0 + m) * D3 + tid];
    __syncthreads();

    float a0[8], a1[8], a2[8];
#pragma unroll
    for (int m = 0; m < 8; m++) { a0[m] = 0.f; a1[m] = 0.f; a2[m] = 0.f; }

    const float* F0 = g_Ft + 0 * (DD * D3) + tid;
    const float* F1 = g_Ft + 1 * (DD * D3) + tid;
    const float* F2 = g_Ft + 2 * (DD * D3) + tid;

    float xv[8];
#pragma unroll 4
    for (int k = 0; k < DD; k++) {
        float w0 = F0[k * D3];
        float w1 = F1[k * D3];
        float w2 = F2[k * D3];
        LOAD8(xv, &sx[k][0]);
#pragma unroll
        for (int m = 0; m < 8; m++) a0[m] = fmaf(xv[m], w0, a0[m]);
        LOAD8(xv, &sx[128 + k][0]);
#pragma unroll
        for (int m = 0; m < 8; m++) a1[m] = fmaf(xv[m], w1, a1[m]);
        LOAD8(xv, &sx[256 + k][0]);
#pragma unroll
        for (int m = 0; m < 8; m++) a2[m] = fmaf(xv[m], w2, a2[m]);
    }
    const float b0 = g_fb[tid], b1 = g_fb[D3 + tid], b2 = g_fb[2 * D3 + tid];
#pragma unroll
    for (int m = 0; m < 8; m++) {
        float* q = g_QKV + (t0 + m) * D9;
        q[tid]          = a0[m] + b0;
        q[D3 + tid]     = a1[m] + b1;
        q[2 * D3 + tid] = a2[m] + b2;
    }
}

// -------------------- K2: prefix-band attention ------------------------------
// s_ij = 0.5 + 0.5*tanh(q_i * c_j), c_j = 2.5*k_j; tanh saturates |x|>6.5.
// Sort elements by |c| (counting sort) -> each query's band is a PREFIX [0,n).
// Tail (|c| >= th): tanh ~ sign(q)*sign(c) -> prefix sums of (sign, sign*v).
// Sort queries by n so warp lanes share band length -> broadcast LDS loop.
__global__ __launch_bounds__(384) void k_attn() {
    __shared__ float2 s[D3];             // |c|-sorted (c, v)
    __shared__ float2 P[D3 + 1];         // prefix of (sign(c), sign(c)*v)
    __shared__ int    off[NBINS + 1];    // element bin offsets
    __shared__ int    cnt[NBINS];
    __shared__ int    cur[NBINS];
    __shared__ int    wtot[4];
    __shared__ float2 wsum2[12];
    __shared__ float  rmax[12], rsum[12];
    __shared__ float  s_inv, s_sumv;
    __shared__ float  sqv[D3];           // q per original query index
    __shared__ int    qlist[D3];         // sorted (query idx | n<<16)
    __shared__ float  satt[D3];

    const int t    = blockIdx.x;
    const int tid  = threadIdx.x;
    const int lane = tid & 31, wid = tid >> 5;
    const float* base = g_QKV + t * D9;

    const float q  = base[tid];
    const float c  = base[D3 + tid] * HALF_GAMMA;
    const float v  = base[2 * D3 + tid];
    const float ac = fabsf(c);
    sqv[tid] = q;

    // ---- block reduce: max |c| and sum v ----
    float mx = ac, sv = v;
#pragma unroll
    for (int o = 16; o > 0; o >>= 1) {
        mx = fmaxf(mx, __shfl_down_sync(0xffffffffu, mx, o));
        sv += __shfl_down_sync(0xffffffffu, sv, o);
    }
    if (lane == 0) { rmax[wid] = mx; rsum[wid] = sv; }
    if (tid < NBINS) cnt[tid] = 0;
    __syncthreads();
    if (tid == 0) {
        float m = rmax[0], s2 = rsum[0];
#pragma unroll
        for (int i = 1; i < 12; i++) { m = fmaxf(m, rmax[i]); s2 += rsum[i]; }
        s_inv  = 127.99f / (m + 1e-12f);
        s_sumv = s2;
    }
    __syncthreads();
    const float inv = s_inv;

    // ---- element counting sort by |c| ----
    const int b = (int)(ac * inv);                    // 0..127
    atomicAdd(&cnt[b], 1);
    __syncthreads();
    {
        int xval = (tid < NBINS) ? cnt[tid] : 0;
        int incl = xval;
#pragma unroll
        for (int o = 1; o < 32; o <<= 1) {
            int nb = __shfl_up_sync(0xffffffffu, incl, o);
            if (lane >= o) incl += nb;
        }
        if (tid < NBINS && lane == 31) wtot[wid] = incl;
        __syncthreads();
        if (tid < NBINS) {
            int add = 0;
#pragma unroll
            for (int w = 0; w < 4; w++) if (w < wid) add += wtot[w];
            off[tid + 1] = incl + add;
            cur[tid]     = incl + add - xval;
        }
        if (tid == 0) off[0] = 0;
    }
    __syncthreads();
    {
        int pos = atomicAdd(&cur[b], 1);
        s[pos] = make_float2(c, v);
    }
    __syncthreads();

    // ---- fused prefix scan of (sign(c), sign(c)*v) over sorted order ----
    {
        float2 e = s[tid];
        float sg = (e.x >= 0.f) ? 1.f : -1.f;
        float2 incl = make_float2(sg, sg * e.y);
#pragma unroll
        for (int o = 1; o < 32; o <<= 1) {
            float ax = __shfl_up_sync(0xffffffffu, incl.x, o);
            float ay = __shfl_up_sync(0xffffffffu, incl.y, o);
            if (lane >= o) { incl.x += ax; incl.y += ay; }
        }
        if (lane == 31) wsum2[wid] = incl;
        __syncthreads();
        float ax = 0.f, ay = 0.f;
#pragma unroll
        for (int w = 0; w < 12; w++)
            if (w < wid) { ax += wsum2[w].x; ay += wsum2[w].y; }
        P[tid + 1] = make_float2(incl.x + ax, incl.y + ay);
        if (tid == 0) P[0] = make_float2(0.f, 0.f);
    }
    __syncthreads();

    // ---- per-query prefix length n (superset of |c| < 6.5/|q|) ----
    const float th = TANH_SAT / fabsf(q);
    const int   bt = (int)fminf(th * inv, 127.0f);
    const int   n  = off[bt + 1];

    // ---- query counting sort by n (bins of 4, reuse cnt/cur) ----
    if (tid < NBINS) cnt[tid] = 0;
    __syncthreads();
    const int qb = min(NBINS - 1, n >> 2);
    atomicAdd(&cnt[qb], 1);
    __syncthreads();
    {
        int xval = (tid < NBINS) ? cnt[tid] : 0;
        int incl = xval;
#pragma unroll
        for (int o = 1; o < 32; o <<= 1) {
            int nb = __shfl_up_sync(0xffffffffu, incl, o);
            if (lane >= o) incl += nb;
        }
        if (tid < NBINS && lane == 31) wtot[wid] = incl;
        __syncthreads();
        if (tid < NBINS) {
            int add = 0;
#pragma unroll
            for (int w = 0; w < 4; w++) if (w < wid) add += wtot[w];
            cur[tid] = incl + add - xval;
        }
    }
    __syncthreads();
    {
        int qpos = atomicAdd(&cur[qb], 1);
        qlist[qpos] = tid | (n << 16);
    }
    __syncthreads();

    // ---- eval: warp lanes have similar n -> broadcast loop to warp max ----
    const int   e   = qlist[tid];
    const int   qi  = e & 0xFFFF;
    const int   nn  = e >> 16;
    const float qq  = sqv[qi];
    int nmax = nn;
#pragma unroll
    for (int o = 16; o > 0; o >>= 1)
        nmax = max(nmax, __shfl_xor_sync(0xffffffffu, nmax, o));

    float ts = 0.f, tv = 0.f;
#pragma unroll 4
    for (int j = 0; j < nmax; j++) {
        float2 cv = s[j];                            // broadcast LDS.64
        if (j < nn) {
            float tt = fast_tanh(qq * cv.x);
            tv = fmaf(tt, cv.y, tv);
            ts += tt;
        }
    }
    const float sg = (qq >= 0.f) ? 1.f : -1.f;
    float2 Pe = P[D3];
    float2 Pn = P[nn];
    ts += sg * (Pe.x - Pn.x);
    tv += sg * (Pe.y - Pn.y);
    float num = fmaf(0.5f, tv, 0.5f * s_sumv);
    float den = fmaf(0.5f, ts, 192.0f + 1e-8f);
    satt[qi] = num / den;
    __syncthreads();
    g_att[t * D3 + tid] = satt[tid];                 // coalesced
}

// -------------------- K3: h = att @ Wpt + bp, fused LayerNorm ---------------
__global__ __launch_bounds__(384, 2) void k_gemm3ln(const float* __restrict__ bp,
                                                    const float* __restrict__ gn,
                                                    const float* __restrict__ bn,
                                                    float* __restrict__ out) {
    __shared__ float sa[D3][12];
    __shared__ float red[8][13];
    __shared__ float smu[8], srs[8];
    const int t0  = blockIdx.x * 8;
    const int tid = threadIdx.x;
    const int lane = tid & 31, wid = tid >> 5;

#pragma unroll
    for (int m = 0; m < 8; m++)
        sa[tid][m] = g_att[(t0 + m) * D3 + tid];
    __syncthreads();

    float a0[8], a1[8], a2[8];
#pragma unroll
    for (int m = 0; m < 8; m++) { a0[m] = 0.f; a1[m] = 0.f; a2[m] = 0.f; }

    float xv[8];
#pragma unroll 4
    for (int k = 0; k < D3; k++) {
        const float* w = g_Wpt + k * D9 + tid;
        float w0 = w[0];
        float w1 = w[D3];
        float w2 = w[2 * D3];
        LOAD8(xv, &sa[k][0]);
#pragma unroll
        for (int m = 0; m < 8; m++) {
            a0[m] = fmaf(xv[m], w0, a0[m]);
            a1[m] = fmaf(xv[m], w1, a1[m]);
            a2[m] = fmaf(xv[m], w2, a2[m]);
        }
    }
    const float b0 = bp[tid], b1 = bp[D3 + tid], b2 = bp[2 * D3 + tid];
#pragma unroll
    for (int m = 0; m < 8; m++) { a0[m] += b0; a1[m] += b1; a2[m] += b2; }

    // ---- mean ----
#pragma unroll
    for (int m = 0; m < 8; m++) {
        float sred = a0[m] + a1[m] + a2[m];
#pragma unroll
        for (int off = 16; off > 0; off >>= 1)
            sred += __shfl_down_sync(0xffffffffu, sred, off);
        if (lane == 0) red[m][wid] = sred;
    }
    __syncthreads();
    if (tid < 8) {
        float tot = 0.f;
#pragma unroll
        for (int i = 0; i < 12; i++) tot += red[tid][i];
        smu[tid] = tot * (1.0f / 1152.0f);
    }
    __syncthreads();

    // ---- variance (two-pass) ----
#pragma unroll
    for (int m = 0; m < 8; m++) {
        float mu = smu[m];
        float d0 = a0[m] - mu, d1 = a1[m] - mu, d2 = a2[m] - mu;
        float sred = d0 * d0 + d1 * d1 + d2 * d2;
#pragma unroll
        for (int off = 16; off > 0; off >>= 1)
            sred += __shfl_down_sync(0xffffffffu, sred, off);
        if (lane == 0) red[m][wid] = sred;
    }
    __syncthreads();
    if (tid < 8) {
        float tot = 0.f;
#pragma unroll
        for (int i = 0; i < 12; i++) tot += red[tid][i];
        srs[tid] = rsqrtf(tot * (1.0f / 1152.0f) + 1e-5f);
    }
    __syncthreads();

    const float g0 = gn[tid], g1 = gn[D3 + tid], g2 = gn[2 * D3 + tid];
    const float n0 = bn[tid], n1 = bn[D3 + tid], n2 = bn[2 * D3 + tid];
#pragma unroll
    for (int m = 0; m < 8; m++) {
        float mu = smu[m], rs = srs[m];
        float* o = out + (t0 + m) * D9;
        o[tid]          = (a0[m] - mu) * rs * g0 + n0;
        o[D3 + tid]     = (a1[m] - mu) * rs * g1 + n1;
        o[2 * D3 + tid] = (a2[m] - mu) * rs * g2 + n2;
    }
}

// -------------------- launch -------------------------------------------------
extern "C" void kernel_launch(void* const* d_in, const int* in_sizes, int n_in,
                              void* d_out, int out_size) {
    const float* x  = (const float*)d_in[0];
    const float* Wq = (const float*)d_in[1];
    const float* bq = (const float*)d_in[2];
    const float* Sq = (const float*)d_in[3];
    const float* Wk = (const float*)d_in[4];
    const float* bk = (const float*)d_in[5];
    const float* Sk = (const float*)d_in[6];
    const float* Wv = (const float*)d_in[7];
    const float* bv = (const float*)d_in[8];
    const float* Sv = (const float*)d_in[9];
    const float* Wp = (const float*)d_in[10];
    const float* bp = (const float*)d_in[11];
    const float* gn = (const float*)d_in[12];
    const float* bn = (const float*)d_in[13];
    float* out = (float*)d_out;

    // order chosen so the profiled (4th) launch is k_attn again
    k_fuse  <<<dim3(32, 3), 384>>>(Wq, Wk, Wv, Sq, Sk, Sv);
    k_fbias <<<144, 256>>>(Sq, Sk, Sv, bq, bk, bv);
    k_qkv   <<<NTOK / 8, 384>>>(x);
    k_attn  <<<NTOK, 384>>>();
    k_wpt   <<<dim3(12, 36), dim3(32, 8)>>>(Wp);
    k_gemm3ln<<<NTOK / 8, 384>>>(bp, gn, bn, out);
}

// round 8
// speedup vs baseline: 1.5567x; 1.0597x over previous
#include <cuda_runtime.h>
#include <math.h>

// ---------------------------------------------------------------------------
//   B=2, T=1024, D=384 -> d=128, D3=384, D9=1152, NTOK=2048
//   GAMMA=5, EPS_W=1e-8, EPS_N=1e-5
// ---------------------------------------------------------------------------
#define NTOK 2048
#define D3   384
#define D9   1152
#define DD   128
#define HALF_GAMMA 2.5f
#define TANH_SAT 6.5f          // |x|>6.5 -> tanh within 3e-6 of +-1
#define NBINS 128

typedef unsigned long long u64;

// -------------------- device scratch (static, no allocs) -------------------
__device__ float g_Ft  [3 * DD * D3];       // fused softplus(W)^T * S: [g][k(128)][o(384)]
__device__ float g_fb  [3 * D3];            // fused bias  S^T b
__device__ float g_Wpt [D3 * D9];           // softplus(Wp) transposed: [k(384)][o(1152)]
__device__ float g_QKV [NTOK * D9];         // per-token [Q(384) K(384) V(384)]
__device__ float g_att [NTOK * D3];

// -------------------- helpers ----------------------------------------------
__device__ __forceinline__ float sp_fast(float w) {
    return fmaxf(w, 0.0f) + __logf(1.0f + __expf(-fabsf(w)));
}
__device__ __forceinline__ float fast_tanh(float x) {
    float y; asm("tanh.approx.f32 %0, %1;" : "=f"(y) : "f"(x)); return y;
}
// ---- packed fp32x2 (Blackwell FFMA2; exact fp32 math, 2x fma throughput) ----
__device__ __forceinline__ u64 dup2(float w) {
    u64 r; asm("mov.b64 %0, {%1, %1};" : "=l"(r) : "f"(w)); return r;
}
__device__ __forceinline__ float2 unpack2(u64 x) {
    float lo, hi; asm("mov.b64 {%0, %1}, %2;" : "=f"(lo), "=f"(hi) : "l"(x));
    return make_float2(lo, hi);
}
__device__ __forceinline__ void fma2(u64& d, u64 a, u64 b) {
    asm("fma.rn.f32x2 %0, %1, %2, %0;" : "+l"(d) : "l"(a), "l"(b));
}

// -------------------- K0a: fused softplus+mix  Ft[g][k][o] ------------------
__global__ __launch_bounds__(384) void k_fuse(
        const float* __restrict__ Wq, const float* __restrict__ Wk,
        const float* __restrict__ Wv,
        const float* __restrict__ Sq, const float* __restrict__ Sk,
        const float* __restrict__ Sv) {
    __shared__ float4 ssw[D3];
    const int g  = blockIdx.y;
    const int k0 = blockIdx.x * 4;
    const int tid = threadIdx.x;
    const float* W = (g == 0) ? Wq : (g == 1) ? Wk : Wv;
    const float* S = (g == 0) ? Sq : (g == 1) ? Sk : Sv;

    float4 w = *(const float4*)(W + tid * DD + k0);
    w.x = sp_fast(w.x); w.y = sp_fast(w.y); w.z = sp_fast(w.z); w.w = sp_fast(w.w);
    ssw[tid] = w;
    __syncthreads();

    float4 acc = make_float4(0.f, 0.f, 0.f, 0.f);
#pragma unroll 4
    for (int m = 0; m < D3; m++) {
        float s  = S[m * D3 + tid];
        float4 c = ssw[m];
        acc.x = fmaf(s, c.x, acc.x);
        acc.y = fmaf(s, c.y, acc.y);
        acc.z = fmaf(s, c.z, acc.z);
        acc.w = fmaf(s, c.w, acc.w);
    }
    float* dst = g_Ft + g * (DD * D3) + k0 * D3 + tid;
    dst[0]      = acc.x;
    dst[D3]     = acc.y;
    dst[2 * D3] = acc.z;
    dst[3 * D3] = acc.w;
}

// -------------------- K0b: fused bias (one warp per output) -----------------
__global__ void k_fbias(const float* __restrict__ Sq, const float* __restrict__ Sk,
                        const float* __restrict__ Sv,
                        const float* __restrict__ bq, const float* __restrict__ bk,
                        const float* __restrict__ bv) {
    const int w    = (blockIdx.x * blockDim.x + threadIdx.x) >> 5;
    const int lane = threadIdx.x & 31;
    if (w >= 3 * D3) return;
    const int g = w / D3, o = w - g * D3;
    const float* S = (g == 0) ? Sq : (g == 1) ? Sk : Sv;
    const float* b = (g == 0) ? bq : (g == 1) ? bk : bv;
    float acc = 0.0f;
#pragma unroll
    for (int i = 0; i < 12; i++) {
        int m = lane + i * 32;
        acc = fmaf(S[m * D3 + o], b[m], acc);
    }
#pragma unroll
    for (int off = 16; off > 0; off >>= 1)
        acc += __shfl_down_sync(0xffffffffu, acc, off);
    if (lane == 0) g_fb[w] = acc;
}

// -------------------- K0c: softplus(Wp) transposed --------------------------
__global__ void k_wpt(const float* __restrict__ Wp) {
    __shared__ float tile[32][33];
    const int k0 = blockIdx.x * 32;
    const int o0 = blockIdx.y * 32;
    const int tx = threadIdx.x, ty = threadIdx.y;    // 32 x 8
#pragma unroll
    for (int i = 0; i < 32; i += 8)
        tile[ty + i][tx] = Wp[(o0 + ty + i) * D3 + k0 + tx];
    __syncthreads();
#pragma unroll
    for (int i = 0; i < 32; i += 8)
        g_Wpt[(k0 + ty + i) * D9 + o0 + tx] = sp_fast(tile[tx][ty + i]);
}

// -------------------- K1: QKV projection (8 tokens/CTA, FFMA2) --------------
__global__ __launch_bounds__(384, 2) void k_qkv(const float* __restrict__ x) {
    __shared__ float sx[D3][12];                     // 48B rows, 16B aligned
    const int t0  = blockIdx.x * 8;
    const int tid = threadIdx.x;

#pragma unroll
    for (int m = 0; m < 8; m++)
        sx[tid][m] = x[(t0 + m) * D3 + tid];
    __syncthreads();

    u64 A0[4], A1[4], A2[4];
#pragma unroll
    for (int p = 0; p < 4; p++) { A0[p] = 0ULL; A1[p] = 0ULL; A2[p] = 0ULL; }

    const float* F0 = g_Ft + 0 * (DD * D3) + tid;
    const float* F1 = g_Ft + 1 * (DD * D3) + tid;
    const float* F2 = g_Ft + 2 * (DD * D3) + tid;

#pragma unroll 4
    for (int k = 0; k < DD; k++) {
        u64 W0 = dup2(F0[k * D3]);
        u64 W1 = dup2(F1[k * D3]);
        u64 W2 = dup2(F2[k * D3]);
        ulonglong2 xa, xb;
        xa = *(const ulonglong2*)&sx[k][0];          // LDS.128 = 2 token-pairs
        xb = *(const ulonglong2*)&sx[k][4];
        fma2(A0[0], xa.x, W0); fma2(A0[1], xa.y, W0);
        fma2(A0[2], xb.x, W0); fma2(A0[3], xb.y, W0);
        xa = *(const ulonglong2*)&sx[128 + k][0];
        xb = *(const ulonglong2*)&sx[128 + k][4];
        fma2(A1[0], xa.x, W1); fma2(A1[1], xa.y, W1);
        fma2(A1[2], xb.x, W1); fma2(A1[3], xb.y, W1);
        xa = *(const ulonglong2*)&sx[256 + k][0];
        xb = *(const ulonglong2*)&sx[256 + k][4];
        fma2(A2[0], xa.x, W2); fma2(A2[1], xa.y, W2);
        fma2(A2[2], xb.x, W2); fma2(A2[3], xb.y, W2);
    }
    const float b0 = g_fb[tid], b1 = g_fb[D3 + tid], b2 = g_fb[2 * D3 + tid];
#pragma unroll
    for (int p = 0; p < 4; p++) {
        float2 v0 = unpack2(A0[p]);
        float2 v1 = unpack2(A1[p]);
        float2 v2 = unpack2(A2[p]);
        float* qA = g_QKV + (t0 + 2 * p)     * D9;
        float* qB = g_QKV + (t0 + 2 * p + 1) * D9;
        qA[tid]          = v0.x + b0;  qB[tid]          = v0.y + b0;
        qA[D3 + tid]     = v1.x + b1;  qB[D3 + tid]     = v1.y + b1;
        qA[2 * D3 + tid] = v2.x + b2;  qB[2 * D3 + tid] = v2.y + b2;
    }
}

// -------------------- K2: prefix-band attention ------------------------------
// s_ij = 0.5 + 0.5*tanh(q_i * c_j), c_j = 2.5*k_j; tanh saturates |x|>6.5.
// Sort elements by |c| (counting sort) -> each query's band is a PREFIX [0,n).
// Tail (|c| >= th): tanh ~ sign(q)*sign(c) -> prefix sums of (sign, sign*v).
// Sort queries by n so warp lanes share band length -> broadcast LDS loop.
__global__ __launch_bounds__(384) void k_attn() {
    __shared__ float2 s[D3];             // |c|-sorted (c, v)
    __shared__ float2 P[D3 + 1];         // prefix of (sign(c), sign(c)*v)
    __shared__ int    off[NBINS + 1];    // element bin offsets
    __shared__ int    cnt[NBINS];
    __shared__ int    cur[NBINS];
    __shared__ int    wtot[4];
    __shared__ float2 wsum2[12];
    __shared__ float  rmax[12], rsum[12];
    __shared__ float  s_inv, s_sumv;
    __shared__ float  sqv[D3];           // q per original query index
    __shared__ int    qlist[D3];         // sorted (query idx | n<<16)
    __shared__ float  satt[D3];

    const int t    = blockIdx.x;
    const int tid  = threadIdx.x;
    const int lane = tid & 31, wid = tid >> 5;
    const float* base = g_QKV + t * D9;

    const float q  = base[tid];
    const float c  = base[D3 + tid] * HALF_GAMMA;
    const float v  = base[2 * D3 + tid];
    const float ac = fabsf(c);
    sqv[tid] = q;

    // ---- block reduce: max |c| and sum v ----
    float mx = ac, sv = v;
#pragma unroll
    for (int o = 16; o > 0; o >>= 1) {
        mx = fmaxf(mx, __shfl_down_sync(0xffffffffu, mx, o));
        sv += __shfl_down_sync(0xffffffffu, sv, o);
    }
    if (lane == 0) { rmax[wid] = mx; rsum[wid] = sv; }
    if (tid < NBINS) cnt[tid] = 0;
    __syncthreads();
    if (tid == 0) {
        float m = rmax[0], s2 = rsum[0];
#pragma unroll
        for (int i = 1; i < 12; i++) { m = fmaxf(m, rmax[i]); s2 += rsum[i]; }
        s_inv  = 127.99f / (m + 1e-12f);
        s_sumv = s2;
    }
    __syncthreads();
    const float inv = s_inv;

    // ---- element counting sort by |c| ----
    const int b = (int)(ac * inv);                    // 0..127
    atomicAdd(&cnt[b], 1);
    __syncthreads();
    {
        int xval = (tid < NBINS) ? cnt[tid] : 0;
        int incl = xval;
#pragma unroll
        for (int o = 1; o < 32; o <<= 1) {
            int nb = __shfl_up_sync(0xffffffffu, incl, o);
            if (lane >= o) incl += nb;
        }
        if (tid < NBINS && lane == 31) wtot[wid] = incl;
        __syncthreads();
        if (tid < NBINS) {
            int add = 0;
#pragma unroll
            for (int w = 0; w < 4; w++) if (w < wid) add += wtot[w];
            off[tid + 1] = incl + add;
            cur[tid]     = incl + add - xval;
        }
        if (tid == 0) off[0] = 0;
    }
    __syncthreads();
    {
        int pos = atomicAdd(&cur[b], 1);
        s[pos] = make_float2(c, v);
    }
    __syncthreads();

    // ---- fused prefix scan of (sign(c), sign(c)*v) over sorted order ----
    {
        float2 e = s[tid];
        float sg = (e.x >= 0.f) ? 1.f : -1.f;
        float2 incl = make_float2(sg, sg * e.y);
#pragma unroll
        for (int o = 1; o < 32; o <<= 1) {
            float ax = __shfl_up_sync(0xffffffffu, incl.x, o);
            float ay = __shfl_up_sync(0xffffffffu, incl.y, o);
            if (lane >= o) { incl.x += ax; incl.y += ay; }
        }
        if (lane == 31) wsum2[wid] = incl;
        __syncthreads();
        float ax = 0.f, ay = 0.f;
#pragma unroll
        for (int w = 0; w < 12; w++)
            if (w < wid) { ax += wsum2[w].x; ay += wsum2[w].y; }
        P[tid + 1] = make_float2(incl.x + ax, incl.y + ay);
        if (tid == 0) P[0] = make_float2(0.f, 0.f);
    }
    __syncthreads();

    // ---- per-query prefix length n (superset of |c| < 6.5/|q|) ----
    const float th = TANH_SAT / fabsf(q);
    const int   bt = (int)fminf(th * inv, 127.0f);
    const int   n  = off[bt + 1];

    // ---- query counting sort by n (bins of 4, reuse cnt/cur) ----
    if (tid < NBINS) cnt[tid] = 0;
    __syncthreads();
    const int qb = min(NBINS - 1, n >> 2);
    atomicAdd(&cnt[qb], 1);
    __syncthreads();
    {
        int xval = (tid < NBINS) ? cnt[tid] : 0;
        int incl = xval;
#pragma unroll
        for (int o = 1; o < 32; o <<= 1) {
            int nb = __shfl_up_sync(0xffffffffu, incl, o);
            if (lane >= o) incl += nb;
        }
        if (tid < NBINS && lane == 31) wtot[wid] = incl;
        __syncthreads();
        if (tid < NBINS) {
            int add = 0;
#pragma unroll
            for (int w = 0; w < 4; w++) if (w < wid) add += wtot[w];
            cur[tid] = incl + add - xval;
        }
    }
    __syncthreads();
    {
        int qpos = atomicAdd(&cur[qb], 1);
        qlist[qpos] = tid | (n << 16);
    }
    __syncthreads();

    // ---- eval: warp lanes have similar n -> broadcast loop to warp max ----
    const int   e   = qlist[tid];
    const int   qi  = e & 0xFFFF;
    const int   nn  = e >> 16;
    const float qq  = sqv[qi];
    int nmax = nn;
#pragma unroll
    for (int o = 16; o > 0; o >>= 1)
        nmax = max(nmax, __shfl_xor_sync(0xffffffffu, nmax, o));

    float ts = 0.f, tv = 0.f;
#pragma unroll 4
    for (int j = 0; j < nmax; j++) {
        float2 cv = s[j];                            // broadcast LDS.64
        if (j < nn) {
            float tt = fast_tanh(qq * cv.x);
            tv = fmaf(tt, cv.y, tv);
            ts += tt;
        }
    }
    const float sg = (qq >= 0.f) ? 1.f : -1.f;
    float2 Pe = P[D3];
    float2 Pn = P[nn];
    ts += sg * (Pe.x - Pn.x);
    tv += sg * (Pe.y - Pn.y);
    float num = fmaf(0.5f, tv, 0.5f * s_sumv);
    float den = fmaf(0.5f, ts, 192.0f + 1e-8f);
    satt[qi] = num / den;
    __syncthreads();
    g_att[t * D3 + tid] = satt[tid];                 // coalesced
}

// -------------------- K3: h = att @ Wpt + bp (FFMA2), fused LayerNorm -------
__global__ __launch_bounds__(384, 2) void k_gemm3ln(const float* __restrict__ bp,
                                                    const float* __restrict__ gn,
                                                    const float* __restrict__ bn,
                                                    float* __restrict__ out) {
    __shared__ float sa[D3][12];
    __shared__ float red[8][13];
    __shared__ float smu[8], srs[8];
    const int t0  = blockIdx.x * 8;
    const int tid = threadIdx.x;
    const int lane = tid & 31, wid = tid >> 5;

#pragma unroll
    for (int m = 0; m < 8; m++)
        sa[tid][m] = g_att[(t0 + m) * D3 + tid];
    __syncthreads();

    u64 A0[4], A1[4], A2[4];
#pragma unroll
    for (int p = 0; p < 4; p++) { A0[p] = 0ULL; A1[p] = 0ULL; A2[p] = 0ULL; }

#pragma unroll 4
    for (int k = 0; k < D3; k++) {
        const float* w = g_Wpt + k * D9 + tid;
        u64 W0 = dup2(w[0]);
        u64 W1 = dup2(w[D3]);
        u64 W2 = dup2(w[2 * D3]);
        ulonglong2 xa = *(const ulonglong2*)&sa[k][0];   // tokens 0-3 (2 pairs)
        ulonglong2 xb = *(const ulonglong2*)&sa[k][4];   // tokens 4-7
        fma2(A0[0], xa.x, W0); fma2(A0[1], xa.y, W0);
        fma2(A0[2], xb.x, W0); fma2(A0[3], xb.y, W0);
        fma2(A1[0], xa.x, W1); fma2(A1[1], xa.y, W1);
        fma2(A1[2], xb.x, W1); fma2(A1[3], xb.y, W1);
        fma2(A2[0], xa.x, W2); fma2(A2[1], xa.y, W2);
        fma2(A2[2], xb.x, W2); fma2(A2[3], xb.y, W2);
    }

    float a0[8], a1[8], a2[8];
    const float b0 = bp[tid], b1 = bp[D3 + tid], b2 = bp[2 * D3 + tid];
#pragma unroll
    for (int p = 0; p < 4; p++) {
        float2 v0 = unpack2(A0[p]);
        float2 v1 = unpack2(A1[p]);
        float2 v2 = unpack2(A2[p]);
        a0[2 * p] = v0.x + b0; a0[2 * p + 1] = v0.y + b0;
        a1[2 * p] = v1.x + b1; a1[2 * p + 1] = v1.y + b1;
        a2[2 * p] = v2.x + b2; a2[2 * p + 1] = v2.y + b2;
    }

    // ---- mean ----
#pragma unroll
    for (int m = 0; m < 8; m++) {
        float sred = a0[m] + a1[m] + a2[m];
#pragma unroll
        for (int off = 16; off > 0; off >>= 1)
            sred += __shfl_down_sync(0xffffffffu, sred, off);
        if (lane == 0) red[m][wid] = sred;
    }
    __syncthreads();
    if (tid < 8) {
        float tot = 0.f;
#pragma unroll
        for (int i = 0; i < 12; i++) tot += red[tid][i];
        smu[tid] = tot * (1.0f / 1152.0f);
    }
    __syncthreads();

    // ---- variance (two-pass) ----
#pragma unroll
    for (int m = 0; m < 8; m++) {
        float mu = smu[m];
        float d0 = a0[m] - mu, d1 = a1[m] - mu, d2 = a2[m] - mu;
        float sred = d0 * d0 + d1 * d1 + d2 * d2;
#pragma unroll
        for (int off = 16; off > 0; off >>= 1)
            sred += __shfl_down_sync(0xffffffffu, sred, off);
        if (lane == 0) red[m][wid] = sred;
    }
    __syncthreads();
    if (tid < 8) {
        float tot = 0.f;
#pragma unroll
        for (int i = 0; i < 12; i++) tot += red[tid][i];
        srs[tid] = rsqrtf(tot * (1.0f / 1152.0f) + 1e-5f);
    }
    __syncthreads();

    const float g0 = gn[tid], g1 = gn[D3 + tid], g2 = gn[2 * D3 + tid];
    const float n0 = bn[tid], n1 = bn[D3 + tid], n2 = bn[2 * D3 + tid];
#pragma unroll
    for (int m = 0; m < 8; m++) {
        float mu = smu[m], rs = srs[m];
        float* o = out + (t0 + m) * D9;
        o[tid]          = (a0[m] - mu) * rs * g0 + n0;
        o[D3 + tid]     = (a1[m] - mu) * rs * g1 + n1;
        o[2 * D3 + tid] = (a2[m] - mu) * rs * g2 + n2;
    }
}

// -------------------- launch -------------------------------------------------
extern "C" void kernel_launch(void* const* d_in, const int* in_sizes, int n_in,
                              void* d_out, int out_size) {
    const float* x  = (const float*)d_in[0];
    const float* Wq = (const float*)d_in[1];
    const float* bq = (const float*)d_in[2];
    const float* Sq = (const float*)d_in[3];
    const float* Wk = (const float*)d_in[4];
    const float* bk = (const float*)d_in[5];
    const float* Sk = (const float*)d_in[6];
    const float* Wv = (const float*)d_in[7];
    const float* bv = (const float*)d_in[8];
    const float* Sv = (const float*)d_in[9];
    const float* Wp = (const float*)d_in[10];
    const float* bp = (const float*)d_in[11];
    const float* gn = (const float*)d_in[12];
    const float* bn = (const float*)d_in[13];
    float* out = (float*)d_out;

    // order: 4th launch (= profiled) is k_qkv to verify FFMA2 effect
    k_fuse  <<<dim3(32, 3), 384>>>(Wq, Wk, Wv, Sq, Sk, Sv);
    k_fbias <<<144, 256>>>(Sq, Sk, Sv, bq, bk, bv);
    k_wpt   <<<dim3(12, 36), dim3(32, 8)>>>(Wp);
    k_qkv   <<<NTOK / 8, 384>>>(x);
    k_attn  <<<NTOK, 384>>>();
    k_gemm3ln<<<NTOK / 8, 384>>>(bp, gn, bn, out);
}

// round 10
// speedup vs baseline: 1.8175x; 1.1675x over previous
#include <cuda_runtime.h>
#include <cuda_bf16.h>
#include <math.h>
#include <stdint.h>

// ---------------------------------------------------------------------------
//   B=2, T=1024, D=384 -> d=128, D3=384, D9=1152, NTOK=2048
//   GAMMA=5, EPS_W=1e-8, EPS_N=1e-5
// ---------------------------------------------------------------------------
#define NTOK 2048
#define D3   384
#define D9   1152
#define DD   128
#define HALF_GAMMA 2.5f
#define TANH_SAT 6.5f
#define NBINS 128
#define PAD  40              // smem row stride (32 k + 8 pad) -> conflict-free frags

typedef unsigned long long u64;

// -------------------- device scratch (static, no allocs) -------------------
// Weights pre-split to bf16 hi/lo, tile layout [ntile][n(128)][k(128)] plain.
// W1 (qkv, block-diagonal): 9 tiles; tile j uses K-group j/3 of x.
// W2 (Wp^T): 27 tiles [kblk(3)][ntile(9)].
__device__ __align__(16) __nv_bfloat16 g_W1h[9  * 16384];
__device__ __align__(16) __nv_bfloat16 g_W1l[9  * 16384];
__device__ __align__(16) __nv_bfloat16 g_W2h[27 * 16384];
__device__ __align__(16) __nv_bfloat16 g_W2l[27 * 16384];
__device__ float g_fb  [3 * D3];            // fused bias S^T b
__device__ float g_QKV [NTOK * D9];
__device__ float g_att [NTOK * D3];
__device__ float g_h   [NTOK * D9];

// -------------------- helpers ----------------------------------------------
__device__ __forceinline__ float sp_fast(float w) {
    return fmaxf(w, 0.0f) + __logf(1.0f + __expf(-fabsf(w)));
}
__device__ __forceinline__ float fast_tanh(float x) {
    float y; asm("tanh.approx.f32 %0, %1;" : "=f"(y) : "f"(x)); return y;
}
__device__ __forceinline__ void wsplit(float v, uint16_t& h, uint16_t& l) {
    __nv_bfloat16 bh = __float2bfloat16(v);
    h = __bfloat16_as_ushort(bh);
    l = __bfloat16_as_ushort(__float2bfloat16(v - __bfloat162float(bh)));
}
__device__ __forceinline__ uint32_t ld32(const __nv_bfloat16* p, int eoff) {
    return *(const uint32_t*)(p + eoff);
}
// m16n8k16 bf16 MMA (baseline PTX, sm_80+; HMMA on sm_100)
__device__ __forceinline__ void mma16816(float* c, const uint32_t* a,
                                         uint32_t b0, uint32_t b1) {
    asm volatile(
        "mma.sync.aligned.m16n8k16.row.col.f32.bf16.bf16.f32 "
        "{%0,%1,%2,%3}, {%4,%5,%6,%7}, {%8,%9}, {%0,%1,%2,%3};"
        : "+f"(c[0]), "+f"(c[1]), "+f"(c[2]), "+f"(c[3])
        : "r"(a[0]), "r"(a[1]), "r"(a[2]), "r"(a[3]), "r"(b0), "r"(b1));
}

// -------------------- K0a: fused softplus+mix -> W1 tiles (bf16 hi/lo) ------
__global__ __launch_bounds__(384) void k_fuse(
        const float* __restrict__ Wq, const float* __restrict__ Wk,
        const float* __restrict__ Wv,
        const float* __restrict__ Sq, const float* __restrict__ Sk,
        const float* __restrict__ Sv) {
    __shared__ float4 ssw[D3];
    const int g  = blockIdx.y;
    const int k0 = blockIdx.x * 4;
    const int tid = threadIdx.x;
    const float* W = (g == 0) ? Wq : (g == 1) ? Wk : Wv;
    const float* S = (g == 0) ? Sq : (g == 1) ? Sk : Sv;

    float4 w = *(const float4*)(W + tid * DD + k0);
    w.x = sp_fast(w.x); w.y = sp_fast(w.y); w.z = sp_fast(w.z); w.w = sp_fast(w.w);
    ssw[tid] = w;
    __syncthreads();

    float acc[4] = {0.f, 0.f, 0.f, 0.f};
#pragma unroll 4
    for (int m = 0; m < D3; m++) {
        float s  = S[m * D3 + tid];
        float4 c = ssw[m];
        acc[0] = fmaf(s, c.x, acc[0]);
        acc[1] = fmaf(s, c.y, acc[1]);
        acc[2] = fmaf(s, c.z, acc[2]);
        acc[3] = fmaf(s, c.w, acc[3]);
    }
    const int ntile = g * 3 + (tid >> 7);
    const int nr    = tid & 127;
#pragma unroll
    for (int j = 0; j < 4; j++) {
        uint16_t h, l;
        wsplit(acc[j], h, l);
        size_t off = (size_t)ntile * 16384 + nr * 128 + (k0 + j);
        g_W1h[off] = __ushort_as_bfloat16(h);
        g_W1l[off] = __ushort_as_bfloat16(l);
    }
}

// -------------------- K0b: fused bias (one warp per output) -----------------
__global__ void k_fbias(const float* __restrict__ Sq, const float* __restrict__ Sk,
                        const float* __restrict__ Sv,
                        const float* __restrict__ bq, const float* __restrict__ bk,
                        const float* __restrict__ bv) {
    const int w    = (blockIdx.x * blockDim.x + threadIdx.x) >> 5;
    const int lane = threadIdx.x & 31;
    if (w >= 3 * D3) return;
    const int g = w / D3, o = w - g * D3;
    const float* S = (g == 0) ? Sq : (g == 1) ? Sk : Sv;
    const float* b = (g == 0) ? bq : (g == 1) ? bk : bv;
    float acc = 0.0f;
#pragma unroll
    for (int i = 0; i < 12; i++) {
        int m = lane + i * 32;
        acc = fmaf(S[m * D3 + o], b[m], acc);
    }
#pragma unroll
    for (int off = 16; off > 0; off >>= 1)
        acc += __shfl_down_sync(0xffffffffu, acc, off);
    if (lane == 0) g_fb[w] = acc;
}

// -------------------- K0c: softplus(Wp)^T -> W2 tiles (bf16 hi/lo) ----------
__global__ void k_wpt(const float* __restrict__ Wp) {
    __shared__ float tile[32][33];
    const int k0 = blockIdx.x * 32;                  // K: 384/32=12
    const int o0 = blockIdx.y * 32;                  // N: 1152/32=36
    const int tx = threadIdx.x, ty = threadIdx.y;    // 32 x 8
#pragma unroll
    for (int i = 0; i < 32; i += 8)
        tile[ty + i][tx] = Wp[(o0 + ty + i) * D3 + k0 + tx];
    __syncthreads();
#pragma unroll
    for (int i = 0; i < 32; i += 8) {
        int k = k0 + ty + i;
        int o = o0 + tx;
        float v = sp_fast(tile[tx][ty + i]);
        uint16_t h, l;
        wsplit(v, h, l);
        size_t off = (size_t)((k >> 7) * 9 + (o >> 7)) * 16384
                   + (o & 127) * 128 + (k & 127);
        g_W2h[off] = __ushort_as_bfloat16(h);
        g_W2l[off] = __ushort_as_bfloat16(l);
    }
}

// -------------------- K1/K3: HMMA dual-bf16 GEMM -----------------------------
// C[2048,1152] = A[2048,384] @ W[384,1152] + bias  (D = AhBh + AhBl + AlBh)
// mode 0: A=x (block-diag W1: N-tile jn uses K-group jn/3), C=g_QKV, bias=g_fb
// mode 1: A=g_att, W=W2,                                    C=g_h,   bias=bp
__global__ __launch_bounds__(256) void k_gemm_mma(int mode,
                                                  const float* __restrict__ Aext,
                                                  const float* __restrict__ bext) {
    __shared__ __nv_bfloat16 sAh[128 * PAD];
    __shared__ __nv_bfloat16 sAl[128 * PAD];
    __shared__ __nv_bfloat16 sBh[128 * PAD];
    __shared__ __nv_bfloat16 sBl[128 * PAD];

    const int tid  = threadIdx.x;
    const int lane = tid & 31, wid = tid >> 5;
    const int g    = lane >> 2, tig = lane & 3;
    const int wm   = wid & 3,  wn  = wid >> 2;       // warp grid 4(m) x 2(n)
    const int m0   = wm * 32,  n0  = wn * 64;
    const int t0   = blockIdx.x * 128;
    const int jn   = blockIdx.y;                     // N tile 0..8

    const float* A    = (mode == 0) ? Aext : g_att;  // both width 384
    float*       Cout = (mode == 0) ? g_QKV : g_h;
    const float* bias = (mode == 0) ? g_fb  : bext;
    const __nv_bfloat16* Wh = (mode == 0) ? g_W1h : g_W2h;
    const __nv_bfloat16* Wl = (mode == 0) ? g_W1l : g_W2l;
    const int nch = (mode == 0) ? 4 : 12;

    float acc[2][8][4];
#pragma unroll
    for (int f = 0; f < 2; f++)
#pragma unroll
        for (int nf = 0; nf < 8; nf++)
#pragma unroll
            for (int i = 0; i < 4; i++) acc[f][nf][i] = 0.f;

    for (int ch = 0; ch < nch; ch++) {
        const int acol  = (mode == 0) ? ((jn / 3) * 128 + ch * 32) : (ch * 32);
        const int wtile = (mode == 0) ? jn : ((ch >> 2) * 9 + jn);
        const int wcol  = (mode == 0) ? (ch * 32) : ((ch & 3) * 32);

        // ---- stage A chunk: fp32 -> bf16 hi/lo ----
#pragma unroll
        for (int it = 0; it < 4; it++) {
            int idx = tid + it * 256;                // 1024 = 128 rows x 8 float4
            int m  = idx >> 3;
            int k4 = (idx & 7) << 2;
            float4 v = *(const float4*)(A + (size_t)(t0 + m) * D3 + acol + k4);
            uint16_t h0, l0, h1, l1, h2, l2, h3, l3;
            wsplit(v.x, h0, l0); wsplit(v.y, h1, l1);
            wsplit(v.z, h2, l2); wsplit(v.w, h3, l3);
            u64 H = (u64)h0 | ((u64)h1 << 16) | ((u64)h2 << 32) | ((u64)h3 << 48);
            u64 L = (u64)l0 | ((u64)l1 << 16) | ((u64)l2 << 32) | ((u64)l3 << 48);
            *(u64*)(sAh + m * PAD + k4) = H;
            *(u64*)(sAl + m * PAD + k4) = L;
        }
        // ---- stage B chunk: copy pre-split weight tile slice ----
        {
            const uint4* swh = (const uint4*)(Wh + (size_t)wtile * 16384);
            const uint4* swl = (const uint4*)(Wl + (size_t)wtile * 16384);
#pragma unroll
            for (int it = 0; it < 2; it++) {
                int idx = tid + it * 256;            // 512 = 128 rows x 4 uint4
                int r  = idx >> 2;
                int c8 = (idx & 3) << 3;
                int so = r * 16 + ((wcol + c8) >> 3);
                *(uint4*)(sBh + r * PAD + c8) = swh[so];
                *(uint4*)(sBl + r * PAD + c8) = swl[so];
            }
        }
        __syncthreads();

        // ---- compute: 2 k16 steps ----
#pragma unroll
        for (int kk = 0; kk < 32; kk += 16) {
            uint32_t ah[2][4], al[2][4];
#pragma unroll
            for (int f = 0; f < 2; f++) {
                int r0 = m0 + f * 16 + g;
                int co = kk + tig * 2;
                ah[f][0] = ld32(sAh, r0 * PAD + co);
                ah[f][1] = ld32(sAh, (r0 + 8) * PAD + co);
                ah[f][2] = ld32(sAh, r0 * PAD + co + 8);
                ah[f][3] = ld32(sAh, (r0 + 8) * PAD + co + 8);
                al[f][0] = ld32(sAl, r0 * PAD + co);
                al[f][1] = ld32(sAl, (r0 + 8) * PAD + co);
                al[f][2] = ld32(sAl, r0 * PAD + co + 8);
                al[f][3] = ld32(sAl, (r0 + 8) * PAD + co + 8);
            }
#pragma unroll
            for (int nf = 0; nf < 8; nf++) {
                int nb = (n0 + nf * 8 + g) * PAD + kk + tig * 2;
                uint32_t bh0 = ld32(sBh, nb);
                uint32_t bh1 = ld32(sBh, nb + 8);
                uint32_t bl0 = ld32(sBl, nb);
                uint32_t bl1 = ld32(sBl, nb + 8);
#pragma unroll
                for (int f = 0; f < 2; f++) {
                    mma16816(acc[f][nf], ah[f], bh0, bh1);
                    mma16816(acc[f][nf], ah[f], bl0, bl1);
                    mma16816(acc[f][nf], al[f], bh0, bh1);
                }
            }
        }
        __syncthreads();
    }

    // ---- epilogue: bias + store ----
#pragma unroll
    for (int f = 0; f < 2; f++) {
        int row = t0 + m0 + f * 16 + g;
#pragma unroll
        for (int nf = 0; nf < 8; nf++) {
            int col = jn * 128 + n0 + nf * 8 + tig * 2;
            float b0v = bias[col], b1v = bias[col + 1];
            float2 lo = make_float2(acc[f][nf][0] + b0v, acc[f][nf][1] + b1v);
            float2 hi = make_float2(acc[f][nf][2] + b0v, acc[f][nf][3] + b1v);
            *(float2*)(Cout + (size_t)row * D9 + col)       = lo;
            *(float2*)(Cout + (size_t)(row + 8) * D9 + col) = hi;
        }
    }
}

// -------------------- K2: prefix-band attention (unchanged, validated) ------
__global__ __launch_bounds__(384) void k_attn() {
    __shared__ float2 s[D3];
    __shared__ float2 P[D3 + 1];
    __shared__ int    off[NBINS + 1];
    __shared__ int    cnt[NBINS];
    __shared__ int    cur[NBINS];
    __shared__ int    wtot[4];
    __shared__ float2 wsum2[12];
    __shared__ float  rmax[12], rsum[12];
    __shared__ float  s_inv, s_sumv;
    __shared__ float  sqv[D3];
    __shared__ int    qlist[D3];
    __shared__ float  satt[D3];

    const int t    = blockIdx.x;
    const int tid  = threadIdx.x;
    const int lane = tid & 31, wid = tid >> 5;
    const float* base = g_QKV + (size_t)t * D9;

    const float q  = base[tid];
    const float c  = base[D3 + tid] * HALF_GAMMA;
    const float v  = base[2 * D3 + tid];
    const float ac = fabsf(c);
    sqv[tid] = q;

    float mx = ac, sv = v;
#pragma unroll
    for (int o = 16; o > 0; o >>= 1) {
        mx = fmaxf(mx, __shfl_down_sync(0xffffffffu, mx, o));
        sv += __shfl_down_sync(0xffffffffu, sv, o);
    }
    if (lane == 0) { rmax[wid] = mx; rsum[wid] = sv; }
    if (tid < NBINS) cnt[tid] = 0;
    __syncthreads();
    if (tid == 0) {
        float m = rmax[0], s2 = rsum[0];
#pragma unroll
        for (int i = 1; i < 12; i++) { m = fmaxf(m, rmax[i]); s2 += rsum[i]; }
        s_inv  = 127.99f / (m + 1e-12f);
        s_sumv = s2;
    }
    __syncthreads();
    const float inv = s_inv;

    const int b = (int)(ac * inv);
    atomicAdd(&cnt[b], 1);
    __syncthreads();
    {
        int xval = (tid < NBINS) ? cnt[tid] : 0;
        int incl = xval;
#pragma unroll
        for (int o = 1; o < 32; o <<= 1) {
            int nb = __shfl_up_sync(0xffffffffu, incl, o);
            if (lane >= o) incl += nb;
        }
        if (tid < NBINS && lane == 31) wtot[wid] = incl;
        __syncthreads();
        if (tid < NBINS) {
            int add = 0;
#pragma unroll
            for (int w = 0; w < 4; w++) if (w < wid) add += wtot[w];
            off[tid + 1] = incl + add;
            cur[tid]     = incl + add - xval;
        }
        if (tid == 0) off[0] = 0;
    }
    __syncthreads();
    {
        int pos = atomicAdd(&cur[b], 1);
        s[pos] = make_float2(c, v);
    }
    __syncthreads();

    {
        float2 e = s[tid];
        float sg = (e.x >= 0.f) ? 1.f : -1.f;
        float2 incl = make_float2(sg, sg * e.y);
#pragma unroll
        for (int o = 1; o < 32; o <<= 1) {
            float ax = __shfl_up_sync(0xffffffffu, incl.x, o);
            float ay = __shfl_up_sync(0xffffffffu, incl.y, o);
            if (lane >= o) { incl.x += ax; incl.y += ay; }
        }
        if (lane == 31) wsum2[wid] = incl;
        __syncthreads();
        float ax = 0.f, ay = 0.f;
#pragma unroll
        for (int w = 0; w < 12; w++)
            if (w < wid) { ax += wsum2[w].x; ay += wsum2[w].y; }
        P[tid + 1] = make_float2(incl.x + ax, incl.y + ay);
        if (tid == 0) P[0] = make_float2(0.f, 0.f);
    }
    __syncthreads();

    const float th = TANH_SAT / fabsf(q);
    const int   bt = (int)fminf(th * inv, 127.0f);
    const int   n  = off[bt + 1];

    if (tid < NBINS) cnt[tid] = 0;
    __syncthreads();
    const int qb = min(NBINS - 1, n >> 2);
    atomicAdd(&cnt[qb], 1);
    __syncthreads();
    {
        int xval = (tid < NBINS) ? cnt[tid] : 0;
        int incl = xval;
#pragma unroll
        for (int o = 1; o < 32; o <<= 1) {
            int nb = __shfl_up_sync(0xffffffffu, incl, o);
            if (lane >= o) incl += nb;
        }
        if (tid < NBINS && lane == 31) wtot[wid] = incl;
        __syncthreads();
        if (tid < NBINS) {
            int add = 0;
#pragma unroll
            for (int w = 0; w < 4; w++) if (w < wid) add += wtot[w];
            cur[tid] = incl + add - xval;
        }
    }
    __syncthreads();
    {
        int qpos = atomicAdd(&cur[qb], 1);
        qlist[qpos] = tid | (n << 16);
    }
    __syncthreads();

    const int   e   = qlist[tid];
    const int   qi  = e & 0xFFFF;
    const int   nn  = e >> 16;
    const float qq  = sqv[qi];
    int nmax = nn;
#pragma unroll
    for (int o = 16; o > 0; o >>= 1)
        nmax = max(nmax, __shfl_xor_sync(0xffffffffu, nmax, o));

    float ts = 0.f, tv = 0.f;
#pragma unroll 4
    for (int j = 0; j < nmax; j++) {
        float2 cv = s[j];
        if (j < nn) {
            float tt = fast_tanh(qq * cv.x);
            tv = fmaf(tt, cv.y, tv);
            ts += tt;
        }
    }
    const float sg = (qq >= 0.f) ? 1.f : -1.f;
    float2 Pe = P[D3];
    float2 Pn = P[nn];
    ts += sg * (Pe.x - Pn.x);
    tv += sg * (Pe.y - Pn.y);
    float num = fmaf(0.5f, tv, 0.5f * s_sumv);
    float den = fmaf(0.5f, ts, 192.0f + 1e-8f);
    satt[qi] = num / den;
    __syncthreads();
    g_att[(size_t)t * D3 + tid] = satt[tid];
}

// -------------------- K4: LayerNorm over D9, two-pass ------------------------
__global__ __launch_bounds__(384) void k_ln(const float* __restrict__ gn,
                                            const float* __restrict__ bn,
                                            float* __restrict__ out) {
    const int t   = blockIdx.x;
    const int tid = threadIdx.x;
    const float* h = g_h + (size_t)t * D9;

    float v0 = h[tid], v1 = h[D3 + tid], v2 = h[2 * D3 + tid];

    __shared__ float red[12];
    __shared__ float bc[2];
    const int lane = tid & 31, wid = tid >> 5;

    float s = v0 + v1 + v2;
#pragma unroll
    for (int o = 16; o > 0; o >>= 1) s += __shfl_down_sync(0xffffffffu, s, o);
    if (lane == 0) red[wid] = s;
    __syncthreads();
    if (tid == 0) {
        float tot = 0.f;
#pragma unroll
        for (int i = 0; i < 12; i++) tot += red[i];
        bc[0] = tot * (1.0f / 1152.0f);
    }
    __syncthreads();
    const float mu = bc[0];

    float d0 = v0 - mu, d1 = v1 - mu, d2 = v2 - mu;
    float ss = d0 * d0 + d1 * d1 + d2 * d2;
#pragma unroll
    for (int o = 16; o > 0; o >>= 1) ss += __shfl_down_sync(0xffffffffu, ss, o);
    __syncthreads();
    if (lane == 0) red[wid] = ss;
    __syncthreads();
    if (tid == 0) {
        float tot = 0.f;
#pragma unroll
        for (int i = 0; i < 12; i++) tot += red[i];
        bc[1] = rsqrtf(tot * (1.0f / 1152.0f) + 1e-5f);
    }
    __syncthreads();
    const float rs = bc[1];

    float* o = out + (size_t)t * D9;
    o[tid]          = d0 * rs * gn[tid]          + bn[tid];
    o[D3 + tid]     = d1 * rs * gn[D3 + tid]     + bn[D3 + tid];
    o[2 * D3 + tid] = d2 * rs * gn[2 * D3 + tid] + bn[2 * D3 + tid];
}

// -------------------- launch -------------------------------------------------
extern "C" void kernel_launch(void* const* d_in, const int* in_sizes, int n_in,
                              void* d_out, int out_size) {
    const float* x  = (const float*)d_in[0];
    const float* Wq = (const float*)d_in[1];
    const float* bq = (const float*)d_in[2];
    const float* Sq = (const float*)d_in[3];
    const float* Wk = (const float*)d_in[4];
    const float* bk = (const float*)d_in[5];
    const float* Sk = (const float*)d_in[6];
    const float* Wv = (const float*)d_in[7];
    const float* bv = (const float*)d_in[8];
    const float* Sv = (const float*)d_in[9];
    const float* Wp = (const float*)d_in[10];
    const float* bp = (const float*)d_in[11];
    const float* gn = (const float*)d_in[12];
    const float* bn = (const float*)d_in[13];
    float* out = (float*)d_out;

    // order: 4th launch (= profiled) is the stage-1 HMMA GEMM
    k_fuse    <<<dim3(32, 3), 384>>>(Wq, Wk, Wv, Sq, Sk, Sv);
    k_fbias   <<<144, 256>>>(Sq, Sk, Sv, bq, bk, bv);
    k_wpt     <<<dim3(12, 36), dim3(32, 8)>>>(Wp);
    k_gemm_mma<<<dim3(16, 9), 256>>>(0, x, nullptr);
    k_attn    <<<NTOK, 384>>>();
    k_gemm_mma<<<dim3(16, 9), 256>>>(1, nullptr, bp);
    k_ln      <<<NTOK, 384>>>(gn, bn, out);
}

// round 11
// speedup vs baseline: 2.0182x; 1.1104x over previous
#include <cuda_runtime.h>
#include <cuda_bf16.h>
#include <math.h>
#include <stdint.h>

// ---------------------------------------------------------------------------
//   B=2, T=1024, D=384 -> d=128, D3=384, D9=1152, NTOK=2048
//   GAMMA=5, EPS_W=1e-8, EPS_N=1e-5
// ---------------------------------------------------------------------------
#define NTOK 2048
#define D3   384
#define D9   1152
#define DD   128
#define HALF_GAMMA 2.5f
#define TANH_SAT 6.5f
#define NBINS 128
#define PAD  40              // smem row stride (32 k + 8 pad), 80B = 16B-aligned

typedef unsigned long long u64;

// -------------------- device scratch (static, no allocs) -------------------
// Weights pre-split bf16 hi/lo, tiles [ntile][n(128)][k(128)] plain row-major.
__device__ __align__(16) __nv_bfloat16 g_W1h[9  * 16384];
__device__ __align__(16) __nv_bfloat16 g_W1l[9  * 16384];
__device__ __align__(16) __nv_bfloat16 g_W2h[27 * 16384];
__device__ __align__(16) __nv_bfloat16 g_W2l[27 * 16384];
__device__ __align__(16) __nv_bfloat16 g_Xh [NTOK * D3];   // x hi/lo
__device__ __align__(16) __nv_bfloat16 g_Xl [NTOK * D3];
__device__ __align__(16) __nv_bfloat16 g_Ath[NTOK * D3];   // att hi/lo
__device__ __align__(16) __nv_bfloat16 g_Atl[NTOK * D3];
__device__ float g_fb  [3 * D3];
__device__ float g_QKV [NTOK * D9];
__device__ float g_h   [NTOK * D9];

// -------------------- helpers ----------------------------------------------
__device__ __forceinline__ float sp_fast(float w) {
    return fmaxf(w, 0.0f) + __logf(1.0f + __expf(-fabsf(w)));
}
__device__ __forceinline__ float fast_tanh(float x) {
    float y; asm("tanh.approx.f32 %0, %1;" : "=f"(y) : "f"(x)); return y;
}
__device__ __forceinline__ void wsplit(float v, uint16_t& h, uint16_t& l) {
    __nv_bfloat16 bh = __float2bfloat16(v);
    h = __bfloat16_as_ushort(bh);
    l = __bfloat16_as_ushort(__float2bfloat16(v - __bfloat162float(bh)));
}
__device__ __forceinline__ uint32_t ld32(const __nv_bfloat16* p, int eoff) {
    return *(const uint32_t*)(p + eoff);
}
__device__ __forceinline__ void mma16816(float* c, const uint32_t* a,
                                         uint32_t b0, uint32_t b1) {
    asm volatile(
        "mma.sync.aligned.m16n8k16.row.col.f32.bf16.bf16.f32 "
        "{%0,%1,%2,%3}, {%4,%5,%6,%7}, {%8,%9}, {%0,%1,%2,%3};"
        : "+f"(c[0]), "+f"(c[1]), "+f"(c[2]), "+f"(c[3])
        : "r"(a[0]), "r"(a[1]), "r"(a[2]), "r"(a[3]), "r"(b0), "r"(b1));
}

// -------------------- K0a: fused softplus+mix -> W1 tiles -------------------
__global__ __launch_bounds__(384) void k_fuse(
        const float* __restrict__ Wq, const float* __restrict__ Wk,
        const float* __restrict__ Wv,
        const float* __restrict__ Sq, const float* __restrict__ Sk,
        const float* __restrict__ Sv) {
    __shared__ float4 ssw[D3];
    const int g  = blockIdx.y;
    const int k0 = blockIdx.x * 4;
    const int tid = threadIdx.x;
    const float* W = (g == 0) ? Wq : (g == 1) ? Wk : Wv;
    const float* S = (g == 0) ? Sq : (g == 1) ? Sk : Sv;

    float4 w = *(const float4*)(W + tid * DD + k0);
    w.x = sp_fast(w.x); w.y = sp_fast(w.y); w.z = sp_fast(w.z); w.w = sp_fast(w.w);
    ssw[tid] = w;
    __syncthreads();

    float acc[4] = {0.f, 0.f, 0.f, 0.f};
#pragma unroll 4
    for (int m = 0; m < D3; m++) {
        float s  = S[m * D3 + tid];
        float4 c = ssw[m];
        acc[0] = fmaf(s, c.x, acc[0]);
        acc[1] = fmaf(s, c.y, acc[1]);
        acc[2] = fmaf(s, c.z, acc[2]);
        acc[3] = fmaf(s, c.w, acc[3]);
    }
    const int ntile = g * 3 + (tid >> 7);
    const int nr    = tid & 127;
    uint16_t h[4], l[4];
#pragma unroll
    for (int j = 0; j < 4; j++) wsplit(acc[j], h[j], l[j]);
    u64 H = (u64)h[0] | ((u64)h[1] << 16) | ((u64)h[2] << 32) | ((u64)h[3] << 48);
    u64 L = (u64)l[0] | ((u64)l[1] << 16) | ((u64)l[2] << 32) | ((u64)l[3] << 48);
    size_t off = (size_t)ntile * 16384 + nr * 128 + k0;
    *(u64*)(g_W1h + off) = H;                        // one 8B store per array
    *(u64*)(g_W1l + off) = L;
}

// -------------------- K0b: fused bias (one warp per output) -----------------
__global__ void k_fbias(const float* __restrict__ Sq, const float* __restrict__ Sk,
                        const float* __restrict__ Sv,
                        const float* __restrict__ bq, const float* __restrict__ bk,
                        const float* __restrict__ bv) {
    const int w    = (blockIdx.x * blockDim.x + threadIdx.x) >> 5;
    const int lane = threadIdx.x & 31;
    if (w >= 3 * D3) return;
    const int g = w / D3, o = w - g * D3;
    const float* S = (g == 0) ? Sq : (g == 1) ? Sk : Sv;
    const float* b = (g == 0) ? bq : (g == 1) ? bk : bv;
    float acc = 0.0f;
#pragma unroll
    for (int i = 0; i < 12; i++) {
        int m = lane + i * 32;
        acc = fmaf(S[m * D3 + o], b[m], acc);
    }
#pragma unroll
    for (int off = 16; off > 0; off >>= 1)
        acc += __shfl_down_sync(0xffffffffu, acc, off);
    if (lane == 0) g_fb[w] = acc;
}

// -------------------- K0c: softplus(Wp)^T -> W2 tiles (coalesced) -----------
__global__ void k_wpt(const float* __restrict__ Wp) {
    const int k0 = blockIdx.x * 32;                  // 384/32=12
    const int o0 = blockIdx.y * 32;                  // 1152/32=36
    const int tx = threadIdx.x, ty = threadIdx.y;    // 32 x 8; tx = k (contig)
#pragma unroll
    for (int i = 0; i < 32; i += 8) {
        int o = o0 + ty + i;
        int k = k0 + tx;
        float v = sp_fast(Wp[o * D3 + k]);           // coalesced read over tx
        uint16_t h, l;
        wsplit(v, h, l);
        size_t off = (size_t)((k >> 7) * 9 + (o >> 7)) * 16384
                   + (o & 127) * 128 + (k & 127);    // coalesced write over tx
        g_W2h[off] = __ushort_as_bfloat16(h);
        g_W2l[off] = __ushort_as_bfloat16(l);
    }
}

// -------------------- K0d: x -> bf16 hi/lo ----------------------------------
__global__ void k_xsplit(const float* __restrict__ x) {
    int i = blockIdx.x * blockDim.x + threadIdx.x;   // 196608 float4s
    float4 v = ((const float4*)x)[i];
    uint16_t h0, l0, h1, l1, h2, l2, h3, l3;
    wsplit(v.x, h0, l0); wsplit(v.y, h1, l1);
    wsplit(v.z, h2, l2); wsplit(v.w, h3, l3);
    ((u64*)g_Xh)[i] = (u64)h0 | ((u64)h1 << 16) | ((u64)h2 << 32) | ((u64)h3 << 48);
    ((u64*)g_Xl)[i] = (u64)l0 | ((u64)l1 << 16) | ((u64)l2 << 32) | ((u64)l3 << 48);
}

// -------------------- K1/K3: HMMA dual-bf16 GEMM (reg double-buffer) --------
// C[2048,1152] = A[2048,384] @ W[384,1152] + bias  (AhBh + AhBl + AlBh)
__global__ __launch_bounds__(256) void k_gemm_mma(int mode,
                                                  const float* __restrict__ bext) {
    __shared__ __nv_bfloat16 sAh[128 * PAD];
    __shared__ __nv_bfloat16 sAl[128 * PAD];
    __shared__ __nv_bfloat16 sBh[128 * PAD];
    __shared__ __nv_bfloat16 sBl[128 * PAD];

    const int tid  = threadIdx.x;
    const int lane = tid & 31, wid = tid >> 5;
    const int g    = lane >> 2, tig = lane & 3;
    const int wm   = wid & 3,  wn  = wid >> 2;
    const int m0   = wm * 32,  n0  = wn * 64;
    const int t0   = blockIdx.x * 128;
    const int jn   = blockIdx.y;

    const __nv_bfloat16* Ah = (mode == 0) ? g_Xh  : g_Ath;
    const __nv_bfloat16* Al = (mode == 0) ? g_Xl  : g_Atl;
    const __nv_bfloat16* Wh = (mode == 0) ? g_W1h : g_W2h;
    const __nv_bfloat16* Wl = (mode == 0) ? g_W1l : g_W2l;
    float*       Cout = (mode == 0) ? g_QKV : g_h;
    const float* bias = (mode == 0) ? g_fb  : bext;
    const int nch = (mode == 0) ? 4 : 12;

    float acc[2][8][4];
#pragma unroll
    for (int f = 0; f < 2; f++)
#pragma unroll
        for (int nf = 0; nf < 8; nf++)
#pragma unroll
            for (int i = 0; i < 4; i++) acc[f][nf][i] = 0.f;

    // 8 copy slots/thread: j 0-1 Ah, 2-3 Al, 4-5 Bh, 6-7 Bl; 512 16B segs each
    uint4 pf[8];
    auto ldch = [&](int ch, uint4* p) {
        const int acol  = (mode == 0) ? ((jn / 3) * 128 + ch * 32) : (ch * 32);
        const int wtile = (mode == 0) ? jn : ((ch >> 2) * 9 + jn);
        const int wcol  = (mode == 0) ? (ch * 32) : ((ch & 3) * 32);
        const __nv_bfloat16* Asrc[2] = {Ah, Al};
        const __nv_bfloat16* Bsrc[2] = {Wh, Wl};
#pragma unroll
        for (int j = 0; j < 8; j++) {
            int w2  = ((j & 1) << 8) + tid;
            int row = w2 >> 2, seg = (w2 & 3) << 3;
            const __nv_bfloat16* src;
            if (j < 4) src = Asrc[j >> 1] + (size_t)(t0 + row) * D3 + acol + seg;
            else       src = Bsrc[(j >> 1) - 2] + (size_t)wtile * 16384
                             + row * 128 + wcol + seg;
            p[j] = *(const uint4*)src;
        }
    };
    auto stch = [&](const uint4* p) {
        __nv_bfloat16* dst[4] = {sAh, sAl, sBh, sBl};
#pragma unroll
        for (int j = 0; j < 8; j++) {
            int w2  = ((j & 1) << 8) + tid;
            int row = w2 >> 2, seg = (w2 & 3) << 3;
            *(uint4*)(dst[j >> 1] + row * PAD + seg) = p[j];
        }
    };

    ldch(0, pf);
    for (int ch = 0; ch < nch; ch++) {
        stch(pf);
        __syncthreads();
        if (ch + 1 < nch) ldch(ch + 1, pf);          // overlap with compute

#pragma unroll
        for (int kk = 0; kk < 32; kk += 16) {
            uint32_t ah[2][4], al[2][4];
#pragma unroll
            for (int f = 0; f < 2; f++) {
                int r0 = m0 + f * 16 + g;
                int co = kk + tig * 2;
                ah[f][0] = ld32(sAh, r0 * PAD + co);
                ah[f][1] = ld32(sAh, (r0 + 8) * PAD + co);
                ah[f][2] = ld32(sAh, r0 * PAD + co + 8);
                ah[f][3] = ld32(sAh, (r0 + 8) * PAD + co + 8);
                al[f][0] = ld32(sAl, r0 * PAD + co);
                al[f][1] = ld32(sAl, (r0 + 8) * PAD + co);
                al[f][2] = ld32(sAl, r0 * PAD + co + 8);
                al[f][3] = ld32(sAl, (r0 + 8) * PAD + co + 8);
            }
#pragma unroll
            for (int nf = 0; nf < 8; nf++) {
                int nb = (n0 + nf * 8 + g) * PAD + kk + tig * 2;
                uint32_t bh0 = ld32(sBh, nb);
                uint32_t bh1 = ld32(sBh, nb + 8);
                uint32_t bl0 = ld32(sBl, nb);
                uint32_t bl1 = ld32(sBl, nb + 8);
#pragma unroll
                for (int f = 0; f < 2; f++) {
                    mma16816(acc[f][nf], ah[f], bh0, bh1);
                    mma16816(acc[f][nf], ah[f], bl0, bl1);
                    mma16816(acc[f][nf], al[f], bh0, bh1);
                }
            }
        }
        __syncthreads();
    }

#pragma unroll
    for (int f = 0; f < 2; f++) {
        int row = t0 + m0 + f * 16 + g;
#pragma unroll
        for (int nf = 0; nf < 8; nf++) {
            int col = jn * 128 + n0 + nf * 8 + tig * 2;
            float b0v = bias[col], b1v = bias[col + 1];
            float2 lo = make_float2(acc[f][nf][0] + b0v, acc[f][nf][1] + b1v);
            float2 hi = make_float2(acc[f][nf][2] + b0v, acc[f][nf][3] + b1v);
            *(float2*)(Cout + (size_t)row * D9 + col)       = lo;
            *(float2*)(Cout + (size_t)(row + 8) * D9 + col) = hi;
        }
    }
}

// -------------------- K2: prefix-band attention (merged query sort) ---------
__global__ __launch_bounds__(384) void k_attn() {
    __shared__ float2 s[D3];
    __shared__ float2 P[D3 + 1];
    __shared__ int    off[NBINS + 1];
    __shared__ int    cnt[NBINS],  cur[NBINS];
    __shared__ int    qcnt[NBINS], qcur[NBINS];
    __shared__ int    wtot[4], qwtot[4];
    __shared__ float2 wsum2[12];
    __shared__ float  rmax[12], rsum[12];
    __shared__ float  s_inv, s_sumv;
    __shared__ float  sqv[D3];
    __shared__ int    qlist[D3];
    __shared__ float  satt[D3];

    const int t    = blockIdx.x;
    const int tid  = threadIdx.x;
    const int lane = tid & 31, wid = tid >> 5;
    const float* base = g_QKV + (size_t)t * D9;

    const float q  = base[tid];
    const float c  = base[D3 + tid] * HALF_GAMMA;
    const float v  = base[2 * D3 + tid];
    const float ac = fabsf(c);
    sqv[tid] = q;

    float mx = ac, sv = v;
#pragma unroll
    for (int o = 16; o > 0; o >>= 1) {
        mx = fmaxf(mx, __shfl_down_sync(0xffffffffu, mx, o));
        sv += __shfl_down_sync(0xffffffffu, sv, o);
    }
    if (lane == 0) { rmax[wid] = mx; rsum[wid] = sv; }
    if (tid < NBINS) { cnt[tid] = 0; qcnt[tid] = 0; }
    __syncthreads();
    if (tid == 0) {
        float m = rmax[0], s2 = rsum[0];
#pragma unroll
        for (int i = 1; i < 12; i++) { m = fmaxf(m, rmax[i]); s2 += rsum[i]; }
        s_inv  = 127.99f / (m + 1e-12f);
        s_sumv = s2;
    }
    __syncthreads();
    const float inv = s_inv;

    // counts: element bin b and query bin bt (bt monotone in prefix length n)
    const int b  = (int)(ac * inv);
    const float th = TANH_SAT / fabsf(q);
    const int bt = (int)fminf(th * inv, 127.0f);
    atomicAdd(&cnt[b], 1);
    atomicAdd(&qcnt[bt], 1);
    __syncthreads();

    // dual exclusive scans: warps 0-3 element bins, warps 4-7 query bins
    int xval = 0;
    if (tid < 128)       xval = cnt[tid];
    else if (tid < 256)  xval = qcnt[tid - 128];
    int incl = xval;
#pragma unroll
    for (int o = 1; o < 32; o <<= 1) {
        int nb = __shfl_up_sync(0xffffffffu, incl, o);
        if (lane >= o) incl += nb;
    }
    if (lane == 31) {
        if (wid < 4)      wtot[wid] = incl;
        else if (wid < 8) qwtot[wid - 4] = incl;
    }
    __syncthreads();
    if (tid < 128) {
        int add = 0;
#pragma unroll
        for (int w = 0; w < 4; w++) if (w < wid) add += wtot[w];
        off[tid + 1] = incl + add;
        cur[tid]     = incl + add - xval;
        if (tid == 0) off[0] = 0;
    } else if (tid < 256) {
        int i2 = tid - 128, wq = wid - 4;
        int add = 0;
#pragma unroll
        for (int w = 0; w < 4; w++) if (w < wq) add += qwtot[w];
        qcur[i2] = incl + add - xval;
    }
    __syncthreads();

    // scatter element; scatter query with its prefix length n
    {
        int pos = atomicAdd(&cur[b], 1);
        s[pos] = make_float2(c, v);
        int n  = off[bt + 1];
        int qpos = atomicAdd(&qcur[bt], 1);
        qlist[qpos] = tid | (n << 16);
    }
    __syncthreads();

    // prefix scan of (sign(c), sign(c)*v) over |c|-sorted order
    {
        float2 e = s[tid];
        float sg = (e.x >= 0.f) ? 1.f : -1.f;
        float2 pincl = make_float2(sg, sg * e.y);
#pragma unroll
        for (int o = 1; o < 32; o <<= 1) {
            float ax = __shfl_up_sync(0xffffffffu, pincl.x, o);
            float ay = __shfl_up_sync(0xffffffffu, pincl.y, o);
            if (lane >= o) { pincl.x += ax; pincl.y += ay; }
        }
        if (lane == 31) wsum2[wid] = pincl;
        __syncthreads();
        float ax = 0.f, ay = 0.f;
#pragma unroll
        for (int w = 0; w < 12; w++)
            if (w < wid) { ax += wsum2[w].x; ay += wsum2[w].y; }
        P[tid + 1] = make_float2(pincl.x + ax, pincl.y + ay);
        if (tid == 0) P[0] = make_float2(0.f, 0.f);
    }
    __syncthreads();

    // eval: lanes ordered by bt -> similar n -> broadcast loop to warp max
    const int   e   = qlist[tid];
    const int   qi  = e & 0xFFFF;
    const int   nn  = e >> 16;
    const float qq  = sqv[qi];
    int nmax = nn;
#pragma unroll
    for (int o = 16; o > 0; o >>= 1)
        nmax = max(nmax, __shfl_xor_sync(0xffffffffu, nmax, o));

    float ts = 0.f, tv = 0.f;
#pragma unroll 4
    for (int j = 0; j < nmax; j++) {
        float2 cv = s[j];
        if (j < nn) {
            float tt = fast_tanh(qq * cv.x);
            tv = fmaf(tt, cv.y, tv);
            ts += tt;
        }
    }
    const float sg = (qq >= 0.f) ? 1.f : -1.f;
    float2 Pe = P[D3];
    float2 Pn = P[nn];
    ts += sg * (Pe.x - Pn.x);
    tv += sg * (Pe.y - Pn.y);
    float num = fmaf(0.5f, tv, 0.5f * s_sumv);
    float den = fmaf(0.5f, ts, 192.0f + 1e-8f);
    satt[qi] = num / den;
    __syncthreads();

    // epilogue: split att to bf16 hi/lo for the tensor GEMM
    uint16_t hh, ll;
    wsplit(satt[tid], hh, ll);
    g_Ath[(size_t)t * D3 + tid] = __ushort_as_bfloat16(hh);
    g_Atl[(size_t)t * D3 + tid] = __ushort_as_bfloat16(ll);
}

// -------------------- K4: LayerNorm over D9, two-pass ------------------------
__global__ __launch_bounds__(384) void k_ln(const float* __restrict__ gn,
                                            const float* __restrict__ bn,
                                            float* __restrict__ out) {
    const int t   = blockIdx.x;
    const int tid = threadIdx.x;
    const float* h = g_h + (size_t)t * D9;

    float v0 = h[tid], v1 = h[D3 + tid], v2 = h[2 * D3 + tid];

    __shared__ float red[12];
    __shared__ float bc[2];
    const int lane = tid & 31, wid = tid >> 5;

    float s = v0 + v1 + v2;
#pragma unroll
    for (int o = 16; o > 0; o >>= 1) s += __shfl_down_sync(0xffffffffu, s, o);
    if (lane == 0) red[wid] = s;
    __syncthreads();
    if (tid == 0) {
        float tot = 0.f;
#pragma unroll
        for (int i = 0; i < 12; i++) tot += red[i];
        bc[0] = tot * (1.0f / 1152.0f);
    }
    __syncthreads();
    const float mu = bc[0];

    float d0 = v0 - mu, d1 = v1 - mu, d2 = v2 - mu;
    float ss = d0 * d0 + d1 * d1 + d2 * d2;
#pragma unroll
    for (int o = 16; o > 0; o >>= 1) ss += __shfl_down_sync(0xffffffffu, ss, o);
    __syncthreads();
    if (lane == 0) red[wid] = ss;
    __syncthreads();
    if (tid == 0) {
        float tot = 0.f;
#pragma unroll
        for (int i = 0; i < 12; i++) tot += red[i];
        bc[1] = rsqrtf(tot * (1.0f / 1152.0f) + 1e-5f);
    }
    __syncthreads();
    const float rs = bc[1];

    float* o = out + (size_t)t * D9;
    o[tid]          = d0 * rs * gn[tid]          + bn[tid];
    o[D3 + tid]     = d1 * rs * gn[D3 + tid]     + bn[D3 + tid];
    o[2 * D3 + tid] = d2 * rs * gn[2 * D3 + tid] + bn[2 * D3 + tid];
}

// -------------------- launch -------------------------------------------------
extern "C" void kernel_launch(void* const* d_in, const int* in_sizes, int n_in,
                              void* d_out, int out_size) {
    const float* x  = (const float*)d_in[0];
    const float* Wq = (const float*)d_in[1];
    const float* bq = (const float*)d_in[2];
    const float* Sq = (const float*)d_in[3];
    const float* Wk = (const float*)d_in[4];
    const float* bk = (const float*)d_in[5];
    const float* Sk = (const float*)d_in[6];
    const float* Wv = (const float*)d_in[7];
    const float* bv = (const float*)d_in[8];
    const float* Sv = (const float*)d_in[9];
    const float* Wp = (const float*)d_in[10];
    const float* bp = (const float*)d_in[11];
    const float* gn = (const float*)d_in[12];
    const float* bn = (const float*)d_in[13];
    float* out = (float*)d_out;

    // 8 launches; ncu skip-5 profiles launch #6 = k_attn (merged-sort check)
    k_fuse    <<<dim3(32, 3), 384>>>(Wq, Wk, Wv, Sq, Sk, Sv);
    k_fbias   <<<144, 256>>>(Sq, Sk, Sv, bq, bk, bv);
    k_wpt     <<<dim3(12, 36), dim3(32, 8)>>>(Wp);
    k_xsplit  <<<768, 256>>>(x);
    k_gemm_mma<<<dim3(16, 9), 256>>>(0, nullptr);
    k_attn    <<<NTOK, 384>>>();
    k_gemm_mma<<<dim3(16, 9), 256>>>(1, bp);
    k_ln      <<<NTOK, 384>>>(gn, bn, out);
}

// round 12
// speedup vs baseline: 2.0910x; 1.0361x over previous
#include <cuda_runtime.h>
#include <cuda_bf16.h>
#include <math.h>
#include <stdint.h>

// ---------------------------------------------------------------------------
//   B=2, T=1024, D=384 -> d=128, D3=384, D9=1152, NTOK=2048
//   GAMMA=5, EPS_W=1e-8, EPS_N=1e-5
// ---------------------------------------------------------------------------
#define NTOK 2048
#define D3   384
#define D9   1152
#define DD   128
#define HALF_GAMMA 2.5f
#define TANH_SAT 5.0f        // |x|>5 -> tanh within 9e-5 of +-1 (tail err ~3e-5 rel)
#define NBINS 128
#define PAD  40              // smem row stride (32 k + 8 pad), 80B = 16B-aligned

typedef unsigned long long u64;

// -------------------- device scratch (static, no allocs) -------------------
__device__ __align__(16) __nv_bfloat16 g_W1h[9  * 16384];
__device__ __align__(16) __nv_bfloat16 g_W1l[9  * 16384];
__device__ __align__(16) __nv_bfloat16 g_W2h[27 * 16384];
__device__ __align__(16) __nv_bfloat16 g_W2l[27 * 16384];
__device__ __align__(16) __nv_bfloat16 g_Ath[NTOK * D3];   // att hi/lo
__device__ __align__(16) __nv_bfloat16 g_Atl[NTOK * D3];
__device__ float g_fb  [3 * D3];
__device__ float g_QKV [NTOK * D9];
__device__ float g_h   [NTOK * D9];

// -------------------- helpers ----------------------------------------------
__device__ __forceinline__ float sp_fast(float w) {
    return fmaxf(w, 0.0f) + __logf(1.0f + __expf(-fabsf(w)));
}
__device__ __forceinline__ float fast_tanh(float x) {
    float y; asm("tanh.approx.f32 %0, %1;" : "=f"(y) : "f"(x)); return y;
}
__device__ __forceinline__ void wsplit(float v, uint16_t& h, uint16_t& l) {
    __nv_bfloat16 bh = __float2bfloat16(v);
    h = __bfloat16_as_ushort(bh);
    l = __bfloat16_as_ushort(__float2bfloat16(v - __bfloat162float(bh)));
}
__device__ __forceinline__ uint32_t ld32(const __nv_bfloat16* p, int eoff) {
    return *(const uint32_t*)(p + eoff);
}
__device__ __forceinline__ void mma16816(float* c, const uint32_t* a,
                                         uint32_t b0, uint32_t b1) {
    asm volatile(
        "mma.sync.aligned.m16n8k16.row.col.f32.bf16.bf16.f32 "
        "{%0,%1,%2,%3}, {%4,%5,%6,%7}, {%8,%9}, {%0,%1,%2,%3};"
        : "+f"(c[0]), "+f"(c[1]), "+f"(c[2]), "+f"(c[3])
        : "r"(a[0]), "r"(a[1]), "r"(a[2]), "r"(a[3]), "r"(b0), "r"(b1));
}

// -------------------- K0a: fused softplus+mix -> W1 tiles -------------------
__global__ __launch_bounds__(384) void k_fuse(
        const float* __restrict__ Wq, const float* __restrict__ Wk,
        const float* __restrict__ Wv,
        const float* __restrict__ Sq, const float* __restrict__ Sk,
        const float* __restrict__ Sv) {
    __shared__ float4 ssw[D3];
    const int g  = blockIdx.y;
    const int k0 = blockIdx.x * 4;
    const int tid = threadIdx.x;
    const float* W = (g == 0) ? Wq : (g == 1) ? Wk : Wv;
    const float* S = (g == 0) ? Sq : (g == 1) ? Sk : Sv;

    float4 w = *(const float4*)(W + tid * DD + k0);
    w.x = sp_fast(w.x); w.y = sp_fast(w.y); w.z = sp_fast(w.z); w.w = sp_fast(w.w);
    ssw[tid] = w;
    __syncthreads();

    float acc[4] = {0.f, 0.f, 0.f, 0.f};
#pragma unroll 4
    for (int m = 0; m < D3; m++) {
        float s  = S[m * D3 + tid];
        float4 c = ssw[m];
        acc[0] = fmaf(s, c.x, acc[0]);
        acc[1] = fmaf(s, c.y, acc[1]);
        acc[2] = fmaf(s, c.z, acc[2]);
        acc[3] = fmaf(s, c.w, acc[3]);
    }
    const int ntile = g * 3 + (tid >> 7);
    const int nr    = tid & 127;
    uint16_t h[4], l[4];
#pragma unroll
    for (int j = 0; j < 4; j++) wsplit(acc[j], h[j], l[j]);
    u64 H = (u64)h[0] | ((u64)h[1] << 16) | ((u64)h[2] << 32) | ((u64)h[3] << 48);
    u64 L = (u64)l[0] | ((u64)l[1] << 16) | ((u64)l[2] << 32) | ((u64)l[3] << 48);
    size_t off = (size_t)ntile * 16384 + nr * 128 + k0;
    *(u64*)(g_W1h + off) = H;
    *(u64*)(g_W1l + off) = L;
}

// -------------------- K0b: merged fbias + Wp tile prep ----------------------
// blocks [0,96): fbias (12 warps each, one warp per output)
// blocks [96,192): softplus(Wp)^T -> W2 tiles, 12 o-rows per block, k=tid
__global__ __launch_bounds__(384) void k_prep2(
        const float* __restrict__ Sq, const float* __restrict__ Sk,
        const float* __restrict__ Sv,
        const float* __restrict__ bq, const float* __restrict__ bk,
        const float* __restrict__ bv,
        const float* __restrict__ Wp) {
    const int tid = threadIdx.x;
    if (blockIdx.x < 96) {
        const int w    = blockIdx.x * 12 + (tid >> 5);   // 0..1151
        const int lane = tid & 31;
        const int g = w / D3, o = w - g * D3;
        const float* S = (g == 0) ? Sq : (g == 1) ? Sk : Sv;
        const float* b = (g == 0) ? bq : (g == 1) ? bk : bv;
        float acc = 0.0f;
#pragma unroll
        for (int i = 0; i < 12; i++) {
            int m = lane + i * 32;
            acc = fmaf(S[m * D3 + o], b[m], acc);
        }
#pragma unroll
        for (int off = 16; off > 0; off >>= 1)
            acc += __shfl_down_sync(0xffffffffu, acc, off);
        if (lane == 0) g_fb[w] = acc;
    } else {
        const int b = blockIdx.x - 96;                   // 0..95
        const int k = tid;                               // contiguous
#pragma unroll
        for (int r = 0; r < 12; r++) {
            int o = b * 12 + r;
            float v = sp_fast(Wp[o * D3 + k]);           // coalesced read
            uint16_t h, l;
            wsplit(v, h, l);
            size_t off = (size_t)((k >> 7) * 9 + (o >> 7)) * 16384
                       + (o & 127) * 128 + (k & 127);    // coalesced (128-chunks)
            g_W2h[off] = __ushort_as_bfloat16(h);
            g_W2l[off] = __ushort_as_bfloat16(l);
        }
    }
}

// -------------------- K1/K3: HMMA dual-bf16 GEMM (reg double-buffer) --------
// C[2048,1152] = A[2048,384] @ W[384,1152] + bias  (AhBh + AhBl + AlBh)
// MODE 0: A = x fp32 (converted inline), W1 block-diag, C=g_QKV, bias=g_fb
// MODE 1: A = g_Ath/g_Atl (pre-split), W2 dense,        C=g_h,   bias=bext
template <int MODE>
__global__ __launch_bounds__(256) void k_gemm_mma(const float* __restrict__ Ax,
                                                  const float* __restrict__ bext) {
    __shared__ __nv_bfloat16 sAh[128 * PAD];
    __shared__ __nv_bfloat16 sAl[128 * PAD];
    __shared__ __nv_bfloat16 sBh[128 * PAD];
    __shared__ __nv_bfloat16 sBl[128 * PAD];

    const int tid  = threadIdx.x;
    const int lane = tid & 31, wid = tid >> 5;
    const int g    = lane >> 2, tig = lane & 3;
    const int wm   = wid & 3,  wn  = wid >> 2;
    const int m0   = wm * 32,  n0  = wn * 64;
    const int t0   = blockIdx.x * 128;
    const int jn   = blockIdx.y;

    const __nv_bfloat16* Wh = (MODE == 0) ? g_W1h : g_W2h;
    const __nv_bfloat16* Wl = (MODE == 0) ? g_W1l : g_W2l;
    float*       Cout = (MODE == 0) ? g_QKV : g_h;
    const float* bias = (MODE == 0) ? g_fb  : bext;
    const int nch = (MODE == 0) ? 4 : 12;

    float acc[2][8][4];
#pragma unroll
    for (int f = 0; f < 2; f++)
#pragma unroll
        for (int nf = 0; nf < 8; nf++)
#pragma unroll
            for (int i = 0; i < 4; i++) acc[f][nf][i] = 0.f;

    float4 afr[4];       // MODE 0: raw fp32 A prefetch
    uint4  pfr[8];       // MODE 1: slots 0-3 A hi/lo; both: 4-7 B hi/lo

    auto ldch = [&](int ch) {
        const int acol  = (MODE == 0) ? ((jn / 3) * 128 + ch * 32) : (ch * 32);
        const int wtile = (MODE == 0) ? jn : ((ch >> 2) * 9 + jn);
        const int wcol  = (MODE == 0) ? (ch * 32) : ((ch & 3) * 32);
        if (MODE == 0) {
#pragma unroll
            for (int j = 0; j < 4; j++) {
                int idx = tid + (j << 8);                // 1024 float4s
                int row = idx >> 3, k4 = (idx & 7) << 2;
                afr[j] = *(const float4*)(Ax + (size_t)(t0 + row) * D3 + acol + k4);
            }
        } else {
#pragma unroll
            for (int j = 0; j < 4; j++) {
                int idx = tid + ((j & 1) << 8);
                int row = idx >> 2, seg = (idx & 3) << 3;
                const __nv_bfloat16* src = ((j < 2) ? g_Ath : g_Atl)
                    + (size_t)(t0 + row) * D3 + acol + seg;
                pfr[j] = *(const uint4*)src;
            }
        }
#pragma unroll
        for (int j = 4; j < 8; j++) {
            int idx = tid + ((j & 1) << 8);
            int row = idx >> 2, seg = (idx & 3) << 3;
            const __nv_bfloat16* src = ((j < 6) ? Wh : Wl)
                + (size_t)wtile * 16384 + row * 128 + wcol + seg;
            pfr[j] = *(const uint4*)src;
        }
    };
    auto stch = [&]() {
        if (MODE == 0) {
#pragma unroll
            for (int j = 0; j < 4; j++) {
                int idx = tid + (j << 8);
                int row = idx >> 3, k4 = (idx & 7) << 2;
                uint16_t h0, l0, h1, l1, h2, l2, h3, l3;
                wsplit(afr[j].x, h0, l0); wsplit(afr[j].y, h1, l1);
                wsplit(afr[j].z, h2, l2); wsplit(afr[j].w, h3, l3);
                u64 H = (u64)h0 | ((u64)h1 << 16) | ((u64)h2 << 32) | ((u64)h3 << 48);
                u64 L = (u64)l0 | ((u64)l1 << 16) | ((u64)l2 << 32) | ((u64)l3 << 48);
                *(u64*)(sAh + row * PAD + k4) = H;
                *(u64*)(sAl + row * PAD + k4) = L;
            }
        } else {
#pragma unroll
            for (int j = 0; j < 4; j++) {
                int idx = tid + ((j & 1) << 8);
                int row = idx >> 2, seg = (idx & 3) << 3;
                *(uint4*)(((j < 2) ? sAh : sAl) + row * PAD + seg) = pfr[j];
            }
        }
#pragma unroll
        for (int j = 4; j < 8; j++) {
            int idx = tid + ((j & 1) << 8);
            int row = idx >> 2, seg = (idx & 3) << 3;
            *(uint4*)(((j < 6) ? sBh : sBl) + row * PAD + seg) = pfr[j];
        }
    };

    ldch(0);
    for (int ch = 0; ch < nch; ch++) {
        stch();
        __syncthreads();
        if (ch + 1 < nch) ldch(ch + 1);                  // overlap with compute

#pragma unroll
        for (int kk = 0; kk < 32; kk += 16) {
            uint32_t ah[2][4], al[2][4];
#pragma unroll
            for (int f = 0; f < 2; f++) {
                int r0 = m0 + f * 16 + g;
                int co = kk + tig * 2;
                ah[f][0] = ld32(sAh, r0 * PAD + co);
                ah[f][1] = ld32(sAh, (r0 + 8) * PAD + co);
                ah[f][2] = ld32(sAh, r0 * PAD + co + 8);
                ah[f][3] = ld32(sAh, (r0 + 8) * PAD + co + 8);
                al[f][0] = ld32(sAl, r0 * PAD + co);
                al[f][1] = ld32(sAl, (r0 + 8) * PAD + co);
                al[f][2] = ld32(sAl, r0 * PAD + co + 8);
                al[f][3] = ld32(sAl, (r0 + 8) * PAD + co + 8);
            }
#pragma unroll
            for (int nf = 0; nf < 8; nf++) {
                int nb = (n0 + nf * 8 + g) * PAD + kk + tig * 2;
                uint32_t bh0 = ld32(sBh, nb);
                uint32_t bh1 = ld32(sBh, nb + 8);
                uint32_t bl0 = ld32(sBl, nb);
                uint32_t bl1 = ld32(sBl, nb + 8);
#pragma unroll
                for (int f = 0; f < 2; f++) {
                    mma16816(acc[f][nf], ah[f], bh0, bh1);
                    mma16816(acc[f][nf], ah[f], bl0, bl1);
                    mma16816(acc[f][nf], al[f], bh0, bh1);
                }
            }
        }
        __syncthreads();
    }

#pragma unroll
    for (int f = 0; f < 2; f++) {
        int row = t0 + m0 + f * 16 + g;
#pragma unroll
        for (int nf = 0; nf < 8; nf++) {
            int col = jn * 128 + n0 + nf * 8 + tig * 2;
            float b0v = bias[col], b1v = bias[col + 1];
            float2 lo = make_float2(acc[f][nf][0] + b0v, acc[f][nf][1] + b1v);
            float2 hi = make_float2(acc[f][nf][2] + b0v, acc[f][nf][3] + b1v);
            *(float2*)(Cout + (size_t)row * D9 + col)       = lo;
            *(float2*)(Cout + (size_t)(row + 8) * D9 + col) = hi;
        }
    }
}

// -------------------- K2: prefix-band attention (merged query sort) ---------
__global__ __launch_bounds__(384) void k_attn() {
    __shared__ float2 s[D3];
    __shared__ float2 P[D3 + 1];
    __shared__ int    off[NBINS + 1];
    __shared__ int    cnt[NBINS],  cur[NBINS];
    __shared__ int    qcnt[NBINS], qcur[NBINS];
    __shared__ int    wtot[4], qwtot[4];
    __shared__ float2 wsum2[12];
    __shared__ float  rmax[12], rsum[12];
    __shared__ float  s_inv, s_sumv;
    __shared__ float  sqv[D3];
    __shared__ int    qlist[D3];
    __shared__ float  satt[D3];

    const int t    = blockIdx.x;
    const int tid  = threadIdx.x;
    const int lane = tid & 31, wid = tid >> 5;
    const float* base = g_QKV + (size_t)t * D9;

    const float q  = base[tid];
    const float c  = base[D3 + tid] * HALF_GAMMA;
    const float v  = base[2 * D3 + tid];
    const float ac = fabsf(c);
    sqv[tid] = q;

    float mx = ac, sv = v;
#pragma unroll
    for (int o = 16; o > 0; o >>= 1) {
        mx = fmaxf(mx, __shfl_down_sync(0xffffffffu, mx, o));
        sv += __shfl_down_sync(0xffffffffu, sv, o);
    }
    if (lane == 0) { rmax[wid] = mx; rsum[wid] = sv; }
    if (tid < NBINS) { cnt[tid] = 0; qcnt[tid] = 0; }
    __syncthreads();
    if (tid == 0) {
        float m = rmax[0], s2 = rsum[0];
#pragma unroll
        for (int i = 1; i < 12; i++) { m = fmaxf(m, rmax[i]); s2 += rsum[i]; }
        s_inv  = 127.99f / (m + 1e-12f);
        s_sumv = s2;
    }
    __syncthreads();
    const float inv = s_inv;

    const int b  = (int)(ac * inv);
    const float th = TANH_SAT / fabsf(q);
    const int bt = (int)fminf(th * inv, 127.0f);
    atomicAdd(&cnt[b], 1);
    atomicAdd(&qcnt[bt], 1);
    __syncthreads();

    // dual exclusive scans: warps 0-3 element bins, warps 4-7 query bins
    int xval = 0;
    if (tid < 128)       xval = cnt[tid];
    else if (tid < 256)  xval = qcnt[tid - 128];
    int incl = xval;
#pragma unroll
    for (int o = 1; o < 32; o <<= 1) {
        int nb = __shfl_up_sync(0xffffffffu, incl, o);
        if (lane >= o) incl += nb;
    }
    if (lane == 31) {
        if (wid < 4)      wtot[wid] = incl;
        else if (wid < 8) qwtot[wid - 4] = incl;
    }
    __syncthreads();
    if (tid < 128) {
        int add = 0;
#pragma unroll
        for (int w = 0; w < 4; w++) if (w < wid) add += wtot[w];
        off[tid + 1] = incl + add;
        cur[tid]     = incl + add - xval;
        if (tid == 0) off[0] = 0;
    } else if (tid < 256) {
        int i2 = tid - 128, wq = wid - 4;
        int add = 0;
#pragma unroll
        for (int w = 0; w < 4; w++) if (w < wq) add += qwtot[w];
        qcur[i2] = incl + add - xval;
    }
    __syncthreads();

    {
        int pos = atomicAdd(&cur[b], 1);
        s[pos] = make_float2(c, v);
        int n  = off[bt + 1];
        int qpos = atomicAdd(&qcur[bt], 1);
        qlist[qpos] = tid | (n << 16);
    }
    __syncthreads();

    {
        float2 e = s[tid];
        float sg = (e.x >= 0.f) ? 1.f : -1.f;
        float2 pincl = make_float2(sg, sg * e.y);
#pragma unroll
        for (int o = 1; o < 32; o <<= 1) {
            float ax = __shfl_up_sync(0xffffffffu, pincl.x, o);
            float ay = __shfl_up_sync(0xffffffffu, pincl.y, o);
            if (lane >= o) { pincl.x += ax; pincl.y += ay; }
        }
        if (lane == 31) wsum2[wid] = pincl;
        __syncthreads();
        float ax = 0.f, ay = 0.f;
#pragma unroll
        for (int w = 0; w < 12; w++)
            if (w < wid) { ax += wsum2[w].x; ay += wsum2[w].y; }
        P[tid + 1] = make_float2(pincl.x + ax, pincl.y + ay);
        if (tid == 0) P[0] = make_float2(0.f, 0.f);
    }
    __syncthreads();

    const int   e   = qlist[tid];
    const int   qi  = e & 0xFFFF;
    const int   nn  = e >> 16;
    const float qq  = sqv[qi];
    int nmax = nn;
#pragma unroll
    for (int o = 16; o > 0; o >>= 1)
        nmax = max(nmax, __shfl_xor_sync(0xffffffffu, nmax, o));

    float ts = 0.f, tv = 0.f;
#pragma unroll 4
    for (int j = 0; j < nmax; j++) {
        float2 cv = s[j];
        if (j < nn) {
            float tt = fast_tanh(qq * cv.x);
            tv = fmaf(tt, cv.y, tv);
            ts += tt;
        }
    }
    const float sg = (qq >= 0.f) ? 1.f : -1.f;
    float2 Pe = P[D3];
    float2 Pn = P[nn];
    ts += sg * (Pe.x - Pn.x);
    tv += sg * (Pe.y - Pn.y);
    float num = fmaf(0.5f, tv, 0.5f * s_sumv);
    float den = fmaf(0.5f, ts, 192.0f + 1e-8f);
    satt[qi] = num / den;
    __syncthreads();

    uint16_t hh, ll;
    wsplit(satt[tid], hh, ll);
    g_Ath[(size_t)t * D3 + tid] = __ushort_as_bfloat16(hh);
    g_Atl[(size_t)t * D3 + tid] = __ushort_as_bfloat16(ll);
}

// -------------------- K4: LayerNorm over D9, two-pass ------------------------
__global__ __launch_bounds__(384) void k_ln(const float* __restrict__ gn,
                                            const float* __restrict__ bn,
                                            float* __restrict__ out) {
    const int t   = blockIdx.x;
    const int tid = threadIdx.x;
    const float* h = g_h + (size_t)t * D9;

    float v0 = h[tid], v1 = h[D3 + tid], v2 = h[2 * D3 + tid];

    __shared__ float red[12];
    __shared__ float bc[2];
    const int lane = tid & 31, wid = tid >> 5;

    float s = v0 + v1 + v2;
#pragma unroll
    for (int o = 16; o > 0; o >>= 1) s += __shfl_down_sync(0xffffffffu, s, o);
    if (lane == 0) red[wid] = s;
    __syncthreads();
    if (tid == 0) {
        float tot = 0.f;
#pragma unroll
        for (int i = 0; i < 12; i++) tot += red[i];
        bc[0] = tot * (1.0f / 1152.0f);
    }
    __syncthreads();
    const float mu = bc[0];

    float d0 = v0 - mu, d1 = v1 - mu, d2 = v2 - mu;
    float ss = d0 * d0 + d1 * d1 + d2 * d2;
#pragma unroll
    for (int o = 16; o > 0; o >>= 1) ss += __shfl_down_sync(0xffffffffu, ss, o);
    __syncthreads();
    if (lane == 0) red[wid] = ss;
    __syncthreads();
    if (tid == 0) {
        float tot = 0.f;
#pragma unroll
        for (int i = 0; i < 12; i++) tot += red[i];
        bc[1] = rsqrtf(tot * (1.0f / 1152.0f) + 1e-5f);
    }
    __syncthreads();
    const float rs = bc[1];

    float* o = out + (size_t)t * D9;
    o[tid]          = d0 * rs * gn[tid]          + bn[tid];
    o[D3 + tid]     = d1 * rs * gn[D3 + tid]     + bn[D3 + tid];
    o[2 * D3 + tid] = d2 * rs * gn[2 * D3 + tid] + bn[2 * D3 + tid];
}

// -------------------- launch -------------------------------------------------
extern "C" void kernel_launch(void* const* d_in, const int* in_sizes, int n_in,
                              void* d_out, int out_size) {
    const float* x  = (const float*)d_in[0];
    const float* Wq = (const float*)d_in[1];
    const float* bq = (const float*)d_in[2];
    const float* Sq = (const float*)d_in[3];
    const float* Wk = (const float*)d_in[4];
    const float* bk = (const float*)d_in[5];
    const float* Sk = (const float*)d_in[6];
    const float* Wv = (const float*)d_in[7];
    const float* bv = (const float*)d_in[8];
    const float* Sv = (const float*)d_in[9];
    const float* Wp = (const float*)d_in[10];
    const float* bp = (const float*)d_in[11];
    const float* gn = (const float*)d_in[12];
    const float* bn = (const float*)d_in[13];
    float* out = (float*)d_out;

    // 6 launches; profiled slot (#4) = k_attn
    k_fuse       <<<dim3(32, 3), 384>>>(Wq, Wk, Wv, Sq, Sk, Sv);
    k_prep2      <<<192, 384>>>(Sq, Sk, Sv, bq, bk, bv, Wp);
    k_gemm_mma<0><<<dim3(16, 9), 256>>>(x, nullptr);
    k_attn       <<<NTOK, 384>>>();
    k_gemm_mma<1><<<dim3(16, 9), 256>>>(nullptr, bp);
    k_ln         <<<NTOK, 384>>>(gn, bn, out);
}

// round 13
// speedup vs baseline: 2.2477x; 1.0749x over previous
#include <cuda_runtime.h>
#include <cuda_bf16.h>
#include <math.h>
#include <stdint.h>

// ---------------------------------------------------------------------------
//   B=2, T=1024, D=384 -> d=128, D3=384, D9=1152, NTOK=2048
//   GAMMA=5, EPS_W=1e-8, EPS_N=1e-5
// ---------------------------------------------------------------------------
#define NTOK 2048
#define D3   384
#define D9   1152
#define DD   128
#define HALF_GAMMA 2.5f
#define TANH_SAT 5.0f        // |x|>5 -> tanh within 9e-5 of +-1
#define NBINS 128
#define PAD  40              // smem row stride (32 k + 8 pad), 80B = 16B-aligned

typedef unsigned long long u64;

// -------------------- device scratch (static, no allocs) -------------------
__device__ __align__(16) __nv_bfloat16 g_W1h[9  * 16384];
__device__ __align__(16) __nv_bfloat16 g_W1l[9  * 16384];
__device__ __align__(16) __nv_bfloat16 g_W2h[27 * 16384];
__device__ __align__(16) __nv_bfloat16 g_W2l[27 * 16384];
__device__ __align__(16) __nv_bfloat16 g_Ath[NTOK * D3];   // att hi/lo
__device__ __align__(16) __nv_bfloat16 g_Atl[NTOK * D3];
__device__ float g_fb  [3 * D3];
__device__ float g_QKV [NTOK * D9];
__device__ float g_h   [NTOK * D9];

// -------------------- helpers ----------------------------------------------
__device__ __forceinline__ float sp_fast(float w) {
    return fmaxf(w, 0.0f) + __logf(1.0f + __expf(-fabsf(w)));
}
__device__ __forceinline__ float fast_tanh(float x) {
    float y; asm("tanh.approx.f32 %0, %1;" : "=f"(y) : "f"(x)); return y;
}
__device__ __forceinline__ void wsplit(float v, uint16_t& h, uint16_t& l) {
    __nv_bfloat16 bh = __float2bfloat16(v);
    h = __bfloat16_as_ushort(bh);
    l = __bfloat16_as_ushort(__float2bfloat16(v - __bfloat162float(bh)));
}
__device__ __forceinline__ uint32_t ld32(const __nv_bfloat16* p, int eoff) {
    return *(const uint32_t*)(p + eoff);
}
__device__ __forceinline__ void mma16816(float* c, const uint32_t* a,
                                         uint32_t b0, uint32_t b1) {
    asm volatile(
        "mma.sync.aligned.m16n8k16.row.col.f32.bf16.bf16.f32 "
        "{%0,%1,%2,%3}, {%4,%5,%6,%7}, {%8,%9}, {%0,%1,%2,%3};"
        : "+f"(c[0]), "+f"(c[1]), "+f"(c[2]), "+f"(c[3])
        : "r"(a[0]), "r"(a[1]), "r"(a[2]), "r"(a[3]), "r"(b0), "r"(b1));
}

// -------------------- K0: merged prep (fuse / fbias / Wp tiles) -------------
// blocks [0,96):    Ft = softplus(W)^T @ S -> W1 tiles (bf16 hi/lo)
// blocks [96,192):  fused bias fb = S^T b (one warp per output)
// blocks [192,288): softplus(Wp)^T -> W2 tiles (coalesced)
__global__ __launch_bounds__(384) void k_prep(
        const float* __restrict__ Wq, const float* __restrict__ Wk,
        const float* __restrict__ Wv,
        const float* __restrict__ Sq, const float* __restrict__ Sk,
        const float* __restrict__ Sv,
        const float* __restrict__ bq, const float* __restrict__ bk,
        const float* __restrict__ bv,
        const float* __restrict__ Wp) {
    __shared__ float4 ssw[D3];
    const int tid = threadIdx.x;
    const int blk = blockIdx.x;

    if (blk < 96) {
        const int g  = blk >> 5;
        const int k0 = (blk & 31) * 4;
        const float* W = (g == 0) ? Wq : (g == 1) ? Wk : Wv;
        const float* S = (g == 0) ? Sq : (g == 1) ? Sk : Sv;

        float4 w = *(const float4*)(W + tid * DD + k0);
        w.x = sp_fast(w.x); w.y = sp_fast(w.y);
        w.z = sp_fast(w.z); w.w = sp_fast(w.w);
        ssw[tid] = w;
        __syncthreads();

        float acc[4] = {0.f, 0.f, 0.f, 0.f};
#pragma unroll 8
        for (int m = 0; m < D3; m++) {
            float s  = S[m * D3 + tid];
            float4 c = ssw[m];
            acc[0] = fmaf(s, c.x, acc[0]);
            acc[1] = fmaf(s, c.y, acc[1]);
            acc[2] = fmaf(s, c.z, acc[2]);
            acc[3] = fmaf(s, c.w, acc[3]);
        }
        const int ntile = g * 3 + (tid >> 7);
        const int nr    = tid & 127;
        uint16_t h[4], l[4];
#pragma unroll
        for (int j = 0; j < 4; j++) wsplit(acc[j], h[j], l[j]);
        u64 H = (u64)h[0] | ((u64)h[1] << 16) | ((u64)h[2] << 32) | ((u64)h[3] << 48);
        u64 L = (u64)l[0] | ((u64)l[1] << 16) | ((u64)l[2] << 32) | ((u64)l[3] << 48);
        size_t off = (size_t)ntile * 16384 + nr * 128 + k0;
        *(u64*)(g_W1h + off) = H;
        *(u64*)(g_W1l + off) = L;
    } else if (blk < 192) {
        const int w    = (blk - 96) * 12 + (tid >> 5);   // 0..1151
        const int lane = tid & 31;
        const int g = w / D3, o = w - g * D3;
        const float* S = (g == 0) ? Sq : (g == 1) ? Sk : Sv;
        const float* b = (g == 0) ? bq : (g == 1) ? bk : bv;
        float acc = 0.0f;
#pragma unroll
        for (int i = 0; i < 12; i++) {
            int m = lane + i * 32;
            acc = fmaf(S[m * D3 + o], b[m], acc);
        }
#pragma unroll
        for (int off = 16; off > 0; off >>= 1)
            acc += __shfl_down_sync(0xffffffffu, acc, off);
        if (lane == 0) g_fb[w] = acc;
    } else {
        const int b = blk - 192;                         // 0..95
        const int k = tid;                               // contiguous
#pragma unroll
        for (int r = 0; r < 12; r++) {
            int o = b * 12 + r;
            float v = sp_fast(Wp[o * D3 + k]);           // coalesced read
            uint16_t h, l;
            wsplit(v, h, l);
            size_t off = (size_t)((k >> 7) * 9 + (o >> 7)) * 16384
                       + (o & 127) * 128 + (k & 127);    // coalesced (128-chunks)
            g_W2h[off] = __ushort_as_bfloat16(h);
            g_W2l[off] = __ushort_as_bfloat16(l);
        }
    }
}

// -------------------- K1/K3: HMMA dual-bf16 GEMM (reg double-buffer) --------
// C[2048,1152] = A[2048,384] @ W[384,1152] + bias  (AhBh + AhBl + AlBh)
// MODE 0: A = x fp32 (converted inline), W1 block-diag, C=g_QKV, bias=g_fb
// MODE 1: A = g_Ath/g_Atl (pre-split), W2 dense,        C=g_h,   bias=bext
template <int MODE>
__global__ __launch_bounds__(256) void k_gemm_mma(const float* __restrict__ Ax,
                                                  const float* __restrict__ bext) {
    __shared__ __nv_bfloat16 sAh[128 * PAD];
    __shared__ __nv_bfloat16 sAl[128 * PAD];
    __shared__ __nv_bfloat16 sBh[128 * PAD];
    __shared__ __nv_bfloat16 sBl[128 * PAD];

    const int tid  = threadIdx.x;
    const int lane = tid & 31, wid = tid >> 5;
    const int g    = lane >> 2, tig = lane & 3;
    const int wm   = wid & 3,  wn  = wid >> 2;
    const int m0   = wm * 32,  n0  = wn * 64;
    const int t0   = blockIdx.x * 128;
    const int jn   = blockIdx.y;

    const __nv_bfloat16* Wh = (MODE == 0) ? g_W1h : g_W2h;
    const __nv_bfloat16* Wl = (MODE == 0) ? g_W1l : g_W2l;
    float*       Cout = (MODE == 0) ? g_QKV : g_h;
    const float* bias = (MODE == 0) ? g_fb  : bext;
    const int nch = (MODE == 0) ? 4 : 12;

    float acc[2][8][4];
#pragma unroll
    for (int f = 0; f < 2; f++)
#pragma unroll
        for (int nf = 0; nf < 8; nf++)
#pragma unroll
            for (int i = 0; i < 4; i++) acc[f][nf][i] = 0.f;

    float4 afr[4];
    uint4  pfr[8];

    auto ldch = [&](int ch) {
        const int acol  = (MODE == 0) ? ((jn / 3) * 128 + ch * 32) : (ch * 32);
        const int wtile = (MODE == 0) ? jn : ((ch >> 2) * 9 + jn);
        const int wcol  = (MODE == 0) ? (ch * 32) : ((ch & 3) * 32);
        if (MODE == 0) {
#pragma unroll
            for (int j = 0; j < 4; j++) {
                int idx = tid + (j << 8);
                int row = idx >> 3, k4 = (idx & 7) << 2;
                afr[j] = *(const float4*)(Ax + (size_t)(t0 + row) * D3 + acol + k4);
            }
        } else {
#pragma unroll
            for (int j = 0; j < 4; j++) {
                int idx = tid + ((j & 1) << 8);
                int row = idx >> 2, seg = (idx & 3) << 3;
                const __nv_bfloat16* src = ((j < 2) ? g_Ath : g_Atl)
                    + (size_t)(t0 + row) * D3 + acol + seg;
                pfr[j] = *(const uint4*)src;
            }
        }
#pragma unroll
        for (int j = 4; j < 8; j++) {
            int idx = tid + ((j & 1) << 8);
            int row = idx >> 2, seg = (idx & 3) << 3;
            const __nv_bfloat16* src = ((j < 6) ? Wh : Wl)
                + (size_t)wtile * 16384 + row * 128 + wcol + seg;
            pfr[j] = *(const uint4*)src;
        }
    };
    auto stch = [&]() {
        if (MODE == 0) {
#pragma unroll
            for (int j = 0; j < 4; j++) {
                int idx = tid + (j << 8);
                int row = idx >> 3, k4 = (idx & 7) << 2;
                uint16_t h0, l0, h1, l1, h2, l2, h3, l3;
                wsplit(afr[j].x, h0, l0); wsplit(afr[j].y, h1, l1);
                wsplit(afr[j].z, h2, l2); wsplit(afr[j].w, h3, l3);
                u64 H = (u64)h0 | ((u64)h1 << 16) | ((u64)h2 << 32) | ((u64)h3 << 48);
                u64 L = (u64)l0 | ((u64)l1 << 16) | ((u64)l2 << 32) | ((u64)l3 << 48);
                *(u64*)(sAh + row * PAD + k4) = H;
                *(u64*)(sAl + row * PAD + k4) = L;
            }
        } else {
#pragma unroll
            for (int j = 0; j < 4; j++) {
                int idx = tid + ((j & 1) << 8);
                int row = idx >> 2, seg = (idx & 3) << 3;
                *(uint4*)(((j < 2) ? sAh : sAl) + row * PAD + seg) = pfr[j];
            }
        }
#pragma unroll
        for (int j = 4; j < 8; j++) {
            int idx = tid + ((j & 1) << 8);
            int row = idx >> 2, seg = (idx & 3) << 3;
            *(uint4*)(((j < 6) ? sBh : sBl) + row * PAD + seg) = pfr[j];
        }
    };

    ldch(0);
    for (int ch = 0; ch < nch; ch++) {
        stch();
        __syncthreads();
        if (ch + 1 < nch) ldch(ch + 1);

#pragma unroll
        for (int kk = 0; kk < 32; kk += 16) {
            uint32_t ah[2][4], al[2][4];
#pragma unroll
            for (int f = 0; f < 2; f++) {
                int r0 = m0 + f * 16 + g;
                int co = kk + tig * 2;
                ah[f][0] = ld32(sAh, r0 * PAD + co);
                ah[f][1] = ld32(sAh, (r0 + 8) * PAD + co);
                ah[f][2] = ld32(sAh, r0 * PAD + co + 8);
                ah[f][3] = ld32(sAh, (r0 + 8) * PAD + co + 8);
                al[f][0] = ld32(sAl, r0 * PAD + co);
                al[f][1] = ld32(sAl, (r0 + 8) * PAD + co);
                al[f][2] = ld32(sAl, r0 * PAD + co + 8);
                al[f][3] = ld32(sAl, (r0 + 8) * PAD + co + 8);
            }
#pragma unroll
            for (int nf = 0; nf < 8; nf++) {
                int nb = (n0 + nf * 8 + g) * PAD + kk + tig * 2;
                uint32_t bh0 = ld32(sBh, nb);
                uint32_t bh1 = ld32(sBh, nb + 8);
                uint32_t bl0 = ld32(sBl, nb);
                uint32_t bl1 = ld32(sBl, nb + 8);
#pragma unroll
                for (int f = 0; f < 2; f++) {
                    mma16816(acc[f][nf], ah[f], bh0, bh1);
                    mma16816(acc[f][nf], ah[f], bl0, bl1);
                    mma16816(acc[f][nf], al[f], bh0, bh1);
                }
            }
        }
        __syncthreads();
    }

#pragma unroll
    for (int f = 0; f < 2; f++) {
        int row = t0 + m0 + f * 16 + g;
#pragma unroll
        for (int nf = 0; nf < 8; nf++) {
            int col = jn * 128 + n0 + nf * 8 + tig * 2;
            float b0v = bias[col], b1v = bias[col + 1];
            float2 lo = make_float2(acc[f][nf][0] + b0v, acc[f][nf][1] + b1v);
            float2 hi = make_float2(acc[f][nf][2] + b0v, acc[f][nf][3] + b1v);
            *(float2*)(Cout + (size_t)row * D9 + col)       = lo;
            *(float2*)(Cout + (size_t)(row + 8) * D9 + col) = hi;
        }
    }
}

// -------------------- K2: prefix-band attention (bin-aggregate tails) -------
// Tail sums now come from per-BIN aggregates (binS, binSV) scanned over 128
// bins by warps 8-11 (previously idle) -- the 384-element float2 prefix scan
// is deleted. Same math: P was only ever read at bin boundaries.
__global__ __launch_bounds__(384) void k_attn() {
    __shared__ float2 s[D3];
    __shared__ int    off[NBINS + 1];
    __shared__ int    cnt[NBINS],  cur[NBINS];
    __shared__ int    qcnt[NBINS], qcur[NBINS];
    __shared__ float  binS[NBINS], binSV[NBINS];
    __shared__ float  PS[NBINS + 1], PSV[NBINS + 1];
    __shared__ int    wtot[4], qwtot[4];
    __shared__ float2 fwtot[4];
    __shared__ float  rmax[12], rsum[12];
    __shared__ float  s_inv, s_sumv;
    __shared__ float  sqv[D3];
    __shared__ int    qlist[D3];
    __shared__ float  satt[D3];

    const int t    = blockIdx.x;
    const int tid  = threadIdx.x;
    const int lane = tid & 31, wid = tid >> 5;
    const float* base = g_QKV + (size_t)t * D9;

    const float q  = base[tid];
    const float c  = base[D3 + tid] * HALF_GAMMA;
    const float v  = base[2 * D3 + tid];
    const float ac = fabsf(c);
    const float sg = (c >= 0.f) ? 1.f : -1.f;
    sqv[tid] = q;

    // block reduce: max |c|, sum v
    float mx = ac, sv = v;
#pragma unroll
    for (int o = 16; o > 0; o >>= 1) {
        mx = fmaxf(mx, __shfl_down_sync(0xffffffffu, mx, o));
        sv += __shfl_down_sync(0xffffffffu, sv, o);
    }
    if (lane == 0) { rmax[wid] = mx; rsum[wid] = sv; }
    if (tid < NBINS) {
        cnt[tid] = 0; qcnt[tid] = 0;
        binS[tid] = 0.f; binSV[tid] = 0.f;
    }
    __syncthreads();
    if (tid == 0) {
        float m = rmax[0], s2 = rsum[0];
#pragma unroll
        for (int i = 1; i < 12; i++) { m = fmaxf(m, rmax[i]); s2 += rsum[i]; }
        s_inv  = 127.99f / (m + 1e-12f);
        s_sumv = s2;
    }
    __syncthreads();
    const float inv = s_inv;

    // counts + bin aggregates
    const int b  = (int)(ac * inv);
    const float th = TANH_SAT / fabsf(q);
    const int bt = (int)fminf(th * inv, 127.0f);
    atomicAdd(&cnt[b], 1);
    atomicAdd(&qcnt[bt], 1);
    atomicAdd(&binS[b], sg);
    atomicAdd(&binSV[b], sg * v);
    __syncthreads();

    // triple scan: warps 0-3 cnt, 4-7 qcnt, 8-11 float2(binS,binSV)
    if (wid < 8) {
        int i2 = tid & 127;
        int xval = (wid < 4) ? cnt[i2] : qcnt[i2];
        int incl = xval;
#pragma unroll
        for (int o = 1; o < 32; o <<= 1) {
            int nb = __shfl_up_sync(0xffffffffu, incl, o);
            if (lane >= o) incl += nb;
        }
        if (lane == 31) {
            if (wid < 4) wtot[wid] = incl;
            else         qwtot[wid - 4] = incl;
        }
        __syncthreads();
        int wq = wid & 3;
        int add = 0;
        const int* tot = (wid < 4) ? wtot : qwtot;
#pragma unroll
        for (int w = 0; w < 4; w++) if (w < wq) add += tot[w];
        if (wid < 4) {
            off[i2 + 1] = incl + add;
            cur[i2]     = incl + add - xval;
            if (i2 == 0) off[0] = 0;
        } else {
            qcur[i2] = incl + add - xval;
        }
    } else {
        int i2 = tid - 256;                               // 0..127
        float fS = binS[i2], fV = binSV[i2];
        float iS = fS, iV = fV;
#pragma unroll
        for (int o = 1; o < 32; o <<= 1) {
            float ax = __shfl_up_sync(0xffffffffu, iS, o);
            float ay = __shfl_up_sync(0xffffffffu, iV, o);
            if (lane >= o) { iS += ax; iV += ay; }
        }
        if (lane == 31) fwtot[wid - 8] = make_float2(iS, iV);
        __syncthreads();
        int wq = wid - 8;
        float aS = 0.f, aV = 0.f;
#pragma unroll
        for (int w = 0; w < 4; w++)
            if (w < wq) { aS += fwtot[w].x; aV += fwtot[w].y; }
        PS [i2 + 1] = iS + aS;
        PSV[i2 + 1] = iV + aV;
        if (i2 == 0) { PS[0] = 0.f; PSV[0] = 0.f; }
    }
    __syncthreads();

    // scatter element; scatter query (qi | n<<9 | bt<<18)
    {
        int pos = atomicAdd(&cur[b], 1);
        s[pos] = make_float2(c, v);
        int n  = off[bt + 1];
        int qpos = atomicAdd(&qcur[bt], 1);
        qlist[qpos] = tid | (n << 9) | (bt << 18);
    }
    __syncthreads();

    // eval: lanes ordered by bt -> similar n -> broadcast loop to warp max
    const int   e   = qlist[tid];
    const int   qi  = e & 511;
    const int   nn  = (e >> 9) & 511;
    const int   btq = (e >> 18) & 127;
    const float qq  = sqv[qi];
    int nmax = nn;
#pragma unroll
    for (int o = 16; o > 0; o >>= 1)
        nmax = max(nmax, __shfl_xor_sync(0xffffffffu, nmax, o));

    float ts = 0.f, tv = 0.f;
#pragma unroll 4
    for (int j = 0; j < nmax; j++) {
        float2 cv = s[j];
        if (j < nn) {
            float tt = fast_tanh(qq * cv.x);
            tv = fmaf(tt, cv.y, tv);
            ts += tt;
        }
    }
    const float sgq = (qq >= 0.f) ? 1.f : -1.f;
    ts += sgq * (PS [NBINS] - PS [btq + 1]);
    tv += sgq * (PSV[NBINS] - PSV[btq + 1]);
    float num = fmaf(0.5f, tv, 0.5f * s_sumv);
    float den = fmaf(0.5f, ts, 192.0f + 1e-8f);
    satt[qi] = num / den;
    __syncthreads();

    uint16_t hh, ll;
    wsplit(satt[tid], hh, ll);
    g_Ath[(size_t)t * D3 + tid] = __ushort_as_bfloat16(hh);
    g_Atl[(size_t)t * D3 + tid] = __ushort_as_bfloat16(ll);
}

// -------------------- K4: LayerNorm, 2 tokens/CTA, two-pass -----------------
__global__ __launch_bounds__(384) void k_ln(const float* __restrict__ gn,
                                            const float* __restrict__ bn,
                                            float* __restrict__ out) {
    __shared__ float red[2][6];
    __shared__ float stat[2][2];
    const int tid  = threadIdx.x;
    const int wid  = tid >> 5, lane = tid & 31;
    const int half = (wid >= 6);
    const int widh = wid - half * 6;
    const int tidh = tid - half * 192;
    const int t    = blockIdx.x * 2 + half;
    const float* h = g_h + (size_t)t * D9;

    float v[6];
#pragma unroll
    for (int j = 0; j < 6; j++) v[j] = h[tidh + 192 * j];

    float s = 0.f;
#pragma unroll
    for (int j = 0; j < 6; j++) s += v[j];
#pragma unroll
    for (int o = 16; o > 0; o >>= 1) s += __shfl_down_sync(0xffffffffu, s, o);
    if (lane == 0) red[half][widh] = s;
    __syncthreads();
    if (tidh == 0) {
        float tot = 0.f;
#pragma unroll
        for (int i = 0; i < 6; i++) tot += red[half][i];
        stat[half][0] = tot * (1.0f / 1152.0f);
    }
    __syncthreads();
    const float mu = stat[half][0];

    float d[6];
    float ss = 0.f;
#pragma unroll
    for (int j = 0; j < 6; j++) { d[j] = v[j] - mu; ss += d[j] * d[j]; }
#pragma unroll
    for (int o = 16; o > 0; o >>= 1) ss += __shfl_down_sync(0xffffffffu, ss, o);
    if (lane == 0) red[half][widh] = ss;
    __syncthreads();
    if (tidh == 0) {
        float tot = 0.f;
#pragma unroll
        for (int i = 0; i < 6; i++) tot += red[half][i];
        stat[half][1] = rsqrtf(tot * (1.0f / 1152.0f) + 1e-5f);
    }
    __syncthreads();
    const float rs = stat[half][1];

    float* o = out + (size_t)t * D9;
#pragma unroll
    for (int j = 0; j < 6; j++) {
        int idx = tidh + 192 * j;
        o[idx] = d[j] * rs * gn[idx] + bn[idx];
    }
}

// -------------------- launch -------------------------------------------------
extern "C" void kernel_launch(void* const* d_in, const int* in_sizes, int n_in,
                              void* d_out, int out_size) {
    const float* x  = (const float*)d_in[0];
    const float* Wq = (const float*)d_in[1];
    const float* bq = (const float*)d_in[2];
    const float* Sq = (const float*)d_in[3];
    const float* Wk = (const float*)d_in[4];
    const float* bk = (const float*)d_in[5];
    const float* Sk = (const float*)d_in[6];
    const float* Wv = (const float*)d_in[7];
    const float* bv = (const float*)d_in[8];
    const float* Sv = (const float*)d_in[9];
    const float* Wp = (const float*)d_in[10];
    const float* bp = (const float*)d_in[11];
    const float* gn = (const float*)d_in[12];
    const float* bn = (const float*)d_in[13];
    float* out = (float*)d_out;

    // 5 launches; profiled slot (#4) = k_gemm_mma<1> (gemm2, post double-buffer)
    k_prep       <<<288, 384>>>(Wq, Wk, Wv, Sq, Sk, Sv, bq, bk, bv, Wp);
    k_gemm_mma<0><<<dim3(16, 9), 256>>>(x, nullptr);
    k_attn       <<<NTOK, 384>>>();
    k_gemm_mma<1><<<dim3(16, 9), 256>>>(nullptr, bp);
    k_ln         <<<NTOK / 2, 384>>>(gn, bn, out);
}